// round 10
// baseline (speedup 1.0000x reference)
#include <cuda_runtime.h>
#include <cuda_bf16.h>
#include <cstdint>

#define M_TOK 8192
#define D_HID 1024
#define F_FEAT 64
#define DFE 128
#define RIN 1152
#define DRH 256
#define NB 4
#define FPB 16
#define ES 4
#define NE 16
#define DEH 512
#define NEH (NE * DEH)

#define OFF_NH 0
#define OFF_GW (M_TOK * D_HID)
#define OFF_GL (OFF_GW + M_TOK * NE)
#define OFF_BW (OFF_GL + M_TOK * NE)
#define OFF_BL (OFF_BW + M_TOK * NB)
#define OFF_SD (OFF_BL + M_TOK * NB)

typedef unsigned long long ull;
typedef __nv_bfloat16 bf16;

// ------------------------- scratch ------------------------------------------
__device__ float g_bh[M_TOK * DRH];
__device__ float g_ih[M_TOK * NB * DRH];
__device__ float g_gate[M_TOK * NE];
__device__ float g_gbias[M_TOK * D_HID];
__device__ bf16 g_ah[M_TOK * D_HID];
__device__ bf16 g_al[M_TOK * D_HID];
__device__ bf16 g_sfe_h[M_TOK * DFE];
__device__ bf16 g_sfe_l[M_TOK * DFE];
__device__ bf16 g_bemb_h[M_TOK * NB * DFE];
__device__ bf16 g_bemb_l[M_TOK * NB * DFE];
__device__ bf16 g_wbr_h[DRH * RIN];       // br_W1^T  [n][k]
__device__ bf16 g_wbr_l[DRH * RIN];
__device__ bf16 g_wir_h[NB * DRH * RIN];  // ir_W1^T  [g*DRH+n][k]
__device__ bf16 g_wir_l[NB * DRH * RIN];
__device__ bf16 g_w1t_h[NEH * D_HID];     // ex_W1^T  [n][k]
__device__ bf16 g_w1t_l[NEH * D_HID];
__device__ bf16 g_w2t_h[D_HID * NEH];     // ex_W2^T  [n][k]
__device__ bf16 g_w2t_l[D_HID * NEH];
__device__ bf16 g_ehh[(size_t)M_TOK * NEH];
__device__ bf16 g_ehl[(size_t)M_TOK * NEH];

// ------------------------- helpers ------------------------------------------
__device__ __forceinline__ float gelu_f(float x) {
    return 0.5f * x * (1.0f + erff(x * 0.70710678118654752440f));
}
__device__ __forceinline__ void split_bf16(float v, bf16& h, bf16& l) {
    h = __float2bfloat16(v);
    l = __float2bfloat16(v - __bfloat162float(h));
}
__device__ __forceinline__ uint32_t smem_u32(const void* p) {
    uint32_t a;
    asm("{ .reg .u64 t; cvta.to.shared.u64 t, %1; cvt.u32.u64 %0, t; }"
        : "=r"(a) : "l"(p));
    return a;
}
__device__ __forceinline__ void cpa16(uint32_t s, const void* g) {
    asm volatile("cp.async.cg.shared.global [%0], [%1], 16;" :: "r"(s), "l"(g));
}
#define CP_COMMIT() asm volatile("cp.async.commit_group;" ::: "memory")
#define CP_WAIT2()  asm volatile("cp.async.wait_group 2;" ::: "memory")
#define CP_WAIT1()  asm volatile("cp.async.wait_group 1;" ::: "memory")
#define CP_WAIT0()  asm volatile("cp.async.wait_group 0;" ::: "memory")

__device__ __forceinline__ void ldsm4(uint32_t* r, uint32_t addr) {
    asm volatile("ldmatrix.sync.aligned.m8n8.x4.shared.b16 {%0,%1,%2,%3}, [%4];"
        : "=r"(r[0]), "=r"(r[1]), "=r"(r[2]), "=r"(r[3]) : "r"(addr));
}
__device__ __forceinline__ void mma16816(float* c, const uint32_t* a, const uint32_t* b) {
    asm volatile("mma.sync.aligned.m16n8k16.row.col.f32.bf16.bf16.f32 "
        "{%0,%1,%2,%3}, {%4,%5,%6,%7}, {%8,%9}, {%0,%1,%2,%3};"
        : "+f"(c[0]), "+f"(c[1]), "+f"(c[2]), "+f"(c[3])
        : "r"(a[0]), "r"(a[1]), "r"(a[2]), "r"(a[3]), "r"(b[0]), "r"(b[1]));
}

// ---------------------------------------------------------------------------
// Kernel 1: LN (bf16 split only) + stage/bundle embeddings (bf16 split)
// ---------------------------------------------------------------------------
__global__ void __launch_bounds__(256) prep_kernel(
    const float* __restrict__ hidden, const float* __restrict__ feat,
    const float* __restrict__ ln_g, const float* __restrict__ ln_b,
    const float* __restrict__ stage_W, const float* __restrict__ stage_b,
    const float* __restrict__ bproj_W, const float* __restrict__ bproj_b)
{
    const int t = blockIdx.x, tid = threadIdx.x;
    __shared__ float red[256];
    __shared__ float sfeat[F_FEAT];
    const float* hrow = hidden + (size_t)t * D_HID;
    float x[4], s = 0.f;
#pragma unroll
    for (int i = 0; i < 4; i++) { x[i] = hrow[tid + 256 * i]; s += x[i]; }
    if (tid < F_FEAT) sfeat[tid] = feat[(size_t)t * F_FEAT + tid];
    red[tid] = s;
    __syncthreads();
    for (int off = 128; off > 0; off >>= 1) {
        if (tid < off) red[tid] += red[tid + off];
        __syncthreads();
    }
    const float mu = red[0] * (1.0f / 1024.0f);
    __syncthreads();
    float v = 0.f;
#pragma unroll
    for (int i = 0; i < 4; i++) { float d = x[i] - mu; v += d * d; }
    red[tid] = v;
    __syncthreads();
    for (int off = 128; off > 0; off >>= 1) {
        if (tid < off) red[tid] += red[tid + off];
        __syncthreads();
    }
    const float rstd = rsqrtf(red[0] * (1.0f / 1024.0f) + 1e-5f);
#pragma unroll
    for (int i = 0; i < 4; i++) {
        int d = tid + 256 * i;
        float hv = (x[i] - mu) * rstd * ln_g[d] + ln_b[d];
        bf16 hi, lo; split_bf16(hv, hi, lo);
        g_ah[(size_t)t * D_HID + d] = hi;
        g_al[(size_t)t * D_HID + d] = lo;
    }
    if (tid < DFE) {
        float acc = stage_b[tid];
#pragma unroll
        for (int f = 0; f < F_FEAT; f++) acc += sfeat[f] * stage_W[f * DFE + tid];
        bf16 hi, lo; split_bf16(acc, hi, lo);
        g_sfe_h[(size_t)t * DFE + tid] = hi;
        g_sfe_l[(size_t)t * DFE + tid] = lo;
    }
    for (int idx = tid; idx < NB * DFE; idx += 256) {
        int g = idx >> 7, j = idx & 127;
        float acc = bproj_b[g * DFE + j];
#pragma unroll
        for (int f = 0; f < FPB; f++)
            acc += sfeat[g * FPB + f] * bproj_W[(g * FPB + f) * DFE + j];
        bf16 hi, lo; split_bf16(acc, hi, lo);
        g_bemb_h[(size_t)t * (NB * DFE) + idx] = hi;
        g_bemb_l[(size_t)t * (NB * DFE) + idx] = lo;
    }
}

// ---------------------------------------------------------------------------
// Transpose + bf16 split.
// W=1: ex_W1[z] (1024x512) -> w1t;  W=2: ex_W2 flat (8192x1024) -> w2t;
// W=3: br_W1 (1152x256) -> wbr;     W=4: ir_W1[z] (1152x256) -> wir.
// ---------------------------------------------------------------------------
template <int W>
__global__ void __launch_bounds__(256) transpose_split(const float* __restrict__ src)
{
    __shared__ float tl[32][33];
    const int z = blockIdx.z;
    const int C = (W == 1) ? DEH : ((W == 2) ? D_HID : DRH);
    const size_t dld = (W == 1) ? D_HID : ((W == 2) ? NEH : RIN);
    const size_t srcz = (W == 1) ? (size_t)D_HID * DEH : ((W == 4) ? (size_t)RIN * DRH : 0);
    const int dstz = (W == 1) ? DEH : ((W == 4) ? DRH : 0);
    const float* s = src + (size_t)z * srcz;
    const int r0 = blockIdx.y * 32, c0 = blockIdx.x * 32;
    const int tx = threadIdx.x & 31, ty = threadIdx.x >> 5;
#pragma unroll
    for (int i = 0; i < 4; i++)
        tl[ty + i * 8][tx] = s[(size_t)(r0 + ty + i * 8) * C + c0 + tx];
    __syncthreads();
#pragma unroll
    for (int i = 0; i < 4; i++) {
        int c = c0 + ty + i * 8;
        float v = tl[tx][ty + i * 8];
        size_t o = ((size_t)z * dstz + c) * dld + r0 + tx;
        bf16 hi, lo; split_bf16(v, hi, lo);
        if (W == 1)      { g_w1t_h[o] = hi; g_w1t_l[o] = lo; }
        else if (W == 2) { g_w2t_h[o] = hi; g_w2t_l[o] = lo; }
        else if (W == 3) { g_wbr_h[o] = hi; g_wbr_l[o] = lo; }
        else             { g_wir_h[o] = hi; g_wir_l[o] = lo; }
    }
}

// ---------------------------------------------------------------------------
// Gate kernel
// ---------------------------------------------------------------------------
__device__ __forceinline__ void top2sm4(const float* s, float* w) {
    float m1 = fmaxf(fmaxf(s[0], s[1]), fmaxf(s[2], s[3]));
    float m2 = -3.0e38f;
    bool used = false;
#pragma unroll
    for (int i = 0; i < 4; i++) {
        if (!used && s[i] == m1) used = true;
        else m2 = fmaxf(m2, s[i]);
    }
    float e[4], den = 0.f;
#pragma unroll
    for (int i = 0; i < 4; i++) {
        e[i] = (s[i] >= m2) ? expf(s[i] - m1) : 0.f;
        den += e[i];
    }
    float inv = 1.0f / den;
#pragma unroll
    for (int i = 0; i < 4; i++) w[i] = e[i] * inv;
}

__global__ void __launch_bounds__(128) gate_kernel(
    const float* __restrict__ br_W2, const float* __restrict__ br_b2,
    const float* __restrict__ ir_W2, const float* __restrict__ ir_b2,
    float* __restrict__ out)
{
    const int t = blockIdx.x, tid = threadIdx.x;
    __shared__ float sbh[DRH];
    __shared__ float sih[NB * DRH];
    __shared__ float slog[20];
    for (int i = tid; i < DRH; i += 128) sbh[i] = g_bh[(size_t)t * DRH + i];
    for (int i = tid; i < NB * DRH; i += 128) sih[i] = g_ih[(size_t)t * NB * DRH + i];
    __syncthreads();
    const int w = tid >> 5, lane = tid & 31;
    for (int d = w; d < 20; d += 4) {
        float s = 0.f;
        if (d < 4) {
            for (int k = lane; k < DRH; k += 32) s += sbh[k] * br_W2[k * NB + d];
        } else {
            int g = (d - 4) >> 2, e = (d - 4) & 3;
            const float* w2 = ir_W2 + g * DRH * ES;
            const float* ihg = sih + g * DRH;
            for (int k = lane; k < DRH; k += 32) s += ihg[k] * w2[k * ES + e];
        }
#pragma unroll
        for (int off = 16; off; off >>= 1) s += __shfl_xor_sync(0xffffffffu, s, off);
        if (lane == 0) slog[d] = s + ((d < 4) ? br_b2[d] : ir_b2[d - 4]);
    }
    __syncthreads();
    if (tid == 0) {
        float bl[4], bw[4], il[16], iw[16];
#pragma unroll
        for (int i = 0; i < 4; i++) bl[i] = slog[i];
#pragma unroll
        for (int i = 0; i < 16; i++) il[i] = slog[4 + i];
        top2sm4(bl, bw);
#pragma unroll
        for (int g = 0; g < 4; g++) top2sm4(&il[g * 4], &iw[g * 4]);
#pragma unroll
        for (int g = 0; g < 4; g++) {
            out[OFF_BW + (size_t)t * NB + g] = bw[g];
            out[OFF_BL + (size_t)t * NB + g] = bl[g];
#pragma unroll
            for (int e = 0; e < 4; e++) {
                int idx = g * 4 + e;
                float gw = bw[g] * iw[idx];
                out[OFF_GW + (size_t)t * NE + idx] = gw;
                out[OFF_GL + (size_t)t * NE + idx] = bl[g] + il[idx];
                g_gate[(size_t)t * NE + idx] = gw;
            }
        }
    }
}

// gbias[t,d] = sum_e gate[t,e] * ex_b2[e,d]
__global__ void __launch_bounds__(256) gbias_kernel(const float* __restrict__ ex_b2)
{
    const int t = blockIdx.x;
    __shared__ float sg[NE];
    if (threadIdx.x < NE) sg[threadIdx.x] = g_gate[(size_t)t * NE + threadIdx.x];
    __syncthreads();
    const int d = threadIdx.x * 4;
    float4 a = {0.f, 0.f, 0.f, 0.f};
#pragma unroll
    for (int e = 0; e < NE; e++) {
        float4 b = *(const float4*)&ex_b2[e * D_HID + d];
        a.x = fmaf(sg[e], b.x, a.x); a.y = fmaf(sg[e], b.y, a.y);
        a.z = fmaf(sg[e], b.z, a.z); a.w = fmaf(sg[e], b.w, a.w);
    }
    *(float4*)&g_gbias[(size_t)t * D_HID + d] = a;
}

// ---------------------------------------------------------------------------
// Shared HMMA machinery, templated on TMI (m-fragments per warp).
// TMI=4 -> CTA tile 128x128; TMI=2 -> CTA tile 64x128.  K-chunk 32.
// 8 warps as 2(m) x 4(n); warp tile (TMI*16) x 32.
// ---------------------------------------------------------------------------
#define LDT 40                        // padded row (32 + 8 bf16)
#define SAB_B 10240                   // B tile bytes: 128*LDT*2

template <int TMI>
__device__ __forceinline__ void load_ab(
    uint32_t sbase, const bf16* __restrict__ Ah, const bf16* __restrict__ Al, int lda,
    const bf16* __restrict__ Bh, const bf16* __restrict__ Bl, int ldb, int tid)
{
    constexpr int AROWS = TMI * 32;
    constexpr int SA = AROWS * LDT * 2;
#pragma unroll
    for (int i = 0; i < AROWS / 64; i++) {
        int q = i * 256 + tid;
        int row = q >> 2, seg = q & 3;
        uint32_t so = (uint32_t)(row * LDT + seg * 8) * 2;
        cpa16(sbase + so,      Ah + (size_t)row * lda + seg * 8);
        cpa16(sbase + SA + so, Al + (size_t)row * lda + seg * 8);
    }
#pragma unroll
    for (int i = 0; i < 2; i++) {
        int q = i * 256 + tid;
        int row = q >> 2, seg = q & 3;
        uint32_t so = (uint32_t)(row * LDT + seg * 8) * 2;
        cpa16(sbase + 2 * SA + so,         Bh + (size_t)row * ldb + seg * 8);
        cpa16(sbase + 2 * SA + SAB_B + so, Bl + (size_t)row * ldb + seg * 8);
    }
}

// 3-term MMA over one resident chunk buffer.
template <int TMI>
__device__ __forceinline__ void chunk_mma(
    float (*acc)[4][4], uint32_t ab, int mw, int nw, int lane)
{
    constexpr int SA = TMI * 32 * LDT * 2;
    const uint32_t bb = ab + 2 * SA;
#pragma unroll
    for (int ks = 0; ks < 32; ks += 16) {
        uint32_t ah[TMI][4], al[TMI][4], bhf[2][4], blf[2][4];
#pragma unroll
        for (int mi = 0; mi < TMI; mi++) {
            uint32_t ra = ab + (uint32_t)((mw + mi * 16 + (lane & 15)) * LDT
                                          + ks + ((lane >> 4) & 1) * 8) * 2;
            ldsm4(ah[mi], ra);
            ldsm4(al[mi], ra + SA);
        }
#pragma unroll
        for (int pj = 0; pj < 2; pj++) {
            uint32_t rb = bb + (uint32_t)((nw + pj * 16 + ((lane >> 4) & 1) * 8
                                           + (lane & 7)) * LDT
                                          + ks + ((lane >> 3) & 1) * 8) * 2;
            ldsm4(bhf[pj], rb);
            ldsm4(blf[pj], rb + SAB_B);
        }
#pragma unroll
        for (int mi = 0; mi < TMI; mi++)
#pragma unroll
            for (int nj = 0; nj < 4; nj++) {
                const int pj = nj >> 1, sb = (nj & 1) * 2;
                mma16816(acc[mi][nj], ah[mi], &bhf[pj][sb]);
                mma16816(acc[mi][nj], ah[mi], &blf[pj][sb]);
                mma16816(acc[mi][nj], al[mi], &bhf[pj][sb]);
            }
    }
}

// ---------------------------------------------------------------------------
// Expert GEMMs, 3-stage cp.async pipeline.
// EPI=1 (TMI=4): ex1, gelu(.+b1)*gate -> eh hi/lo.
// EPI=2 (TMI=2): ex2, combine -> out (64x128 tiles kill the wave tail).
// ---------------------------------------------------------------------------
template <int EPI, int TMI>
__global__ void __launch_bounds__(256) mma_kernel(
    const float* __restrict__ b1, const float* __restrict__ hidden,
    const float* __restrict__ alpha_p, float* __restrict__ out)
{
    extern __shared__ bf16 dsm[];
    const uint32_t sbase = smem_u32(dsm);
    const int tid = threadIdx.x;
    const int wid = tid >> 5, lane = tid & 31;
    constexpr int AROWS = TMI * 32;
    constexpr int STB = 2 * (AROWS * LDT * 2) + 2 * SAB_B;   // stage bytes
    const int m0 = blockIdx.y * AROWS;
    const int n0 = blockIdx.x * 128;

    const int ldk = (EPI == 1) ? D_HID : NEH;
    const bf16* Ah = ((EPI == 1) ? g_ah : g_ehh) + (size_t)m0 * ldk;
    const bf16* Al = ((EPI == 1) ? g_al : g_ehl) + (size_t)m0 * ldk;
    const bf16* Bh = ((EPI == 1) ? g_w1t_h : g_w2t_h) + (size_t)n0 * ldk;
    const bf16* Bl = ((EPI == 1) ? g_w1t_l : g_w2t_l) + (size_t)n0 * ldk;
    const int nchunk = ldk / 32;

    const int mw = (wid >> 2) * (TMI * 16);
    const int nw = (wid & 3) * 32;

    float acc[TMI][4][4];
#pragma unroll
    for (int a = 0; a < TMI; a++)
#pragma unroll
        for (int b = 0; b < 4; b++)
#pragma unroll
            for (int c = 0; c < 4; c++) acc[a][b][c] = 0.f;

    load_ab<TMI>(sbase, Ah, Al, ldk, Bh, Bl, ldk, tid);
    CP_COMMIT();
    load_ab<TMI>(sbase + STB, Ah + 32, Al + 32, ldk, Bh + 32, Bl + 32, ldk, tid);
    CP_COMMIT();

    for (int ci = 0; ci < nchunk; ci++) {
        if (ci + 2 < nchunk) {
            load_ab<TMI>(sbase + ((ci + 2) % 3) * STB,
                         Ah + (ci + 2) * 32, Al + (ci + 2) * 32, ldk,
                         Bh + (ci + 2) * 32, Bl + (ci + 2) * 32, ldk, tid);
            CP_COMMIT();
            CP_WAIT2();
        } else if (ci + 1 < nchunk) {
            CP_WAIT1();
        } else {
            CP_WAIT0();
        }
        __syncthreads();
        chunk_mma<TMI>(acc, sbase + (ci % 3) * STB, mw, nw, lane);
        __syncthreads();
    }

    const int mfrag = mw + (lane >> 2);
    const int nfrag = nw + (lane & 3) * 2;

    if (EPI == 1) {
        const int e = n0 >> 9;
#pragma unroll
        for (int mi = 0; mi < TMI; mi++) {
            const int r0 = m0 + mfrag + mi * 16;
            const float gv0 = g_gate[(size_t)r0 * NE + e];
            const float gv1 = g_gate[(size_t)(r0 + 8) * NE + e];
#pragma unroll
            for (int nj = 0; nj < 4; nj++) {
                const int ng = n0 + nfrag + nj * 8;
                const float* c = acc[mi][nj];
                float o0 = gelu_f(c[0] + b1[ng])     * gv0;
                float o1 = gelu_f(c[1] + b1[ng + 1]) * gv0;
                float o2 = gelu_f(c[2] + b1[ng])     * gv1;
                float o3 = gelu_f(c[3] + b1[ng + 1]) * gv1;
                bf16 h0, l0, h1, l1, h2, l2, h3, l3;
                split_bf16(o0, h0, l0); split_bf16(o1, h1, l1);
                split_bf16(o2, h2, l2); split_bf16(o3, h3, l3);
                *(__nv_bfloat162*)&g_ehh[(size_t)r0 * NEH + ng]       = __halves2bfloat162(h0, h1);
                *(__nv_bfloat162*)&g_ehl[(size_t)r0 * NEH + ng]       = __halves2bfloat162(l0, l1);
                *(__nv_bfloat162*)&g_ehh[(size_t)(r0 + 8) * NEH + ng] = __halves2bfloat162(h2, h3);
                *(__nv_bfloat162*)&g_ehl[(size_t)(r0 + 8) * NEH + ng] = __halves2bfloat162(l2, l3);
            }
        }
    } else {
        const float alpha = *alpha_p;
#pragma unroll
        for (int mi = 0; mi < TMI; mi++) {
            const int r0 = m0 + mfrag + mi * 16;
#pragma unroll
            for (int nj = 0; nj < 4; nj++) {
                const int ng = n0 + nfrag + nj * 8;
                const float* c = acc[mi][nj];
#pragma unroll
                for (int h = 0; h < 2; h++) {
                    const int r = r0 + h * 8;
                    const size_t go = (size_t)r * D_HID + ng;
                    float2 gb = *(const float2*)&g_gbias[go];
                    float2 hv = *(const float2*)&hidden[go];
                    float2 sd, nh;
                    sd.x = c[h * 2]     + gb.x;
                    sd.y = c[h * 2 + 1] + gb.y;
                    nh.x = hv.x + alpha * sd.x;
                    nh.y = hv.y + alpha * sd.y;
                    *(float2*)&out[OFF_SD + go] = sd;
                    *(float2*)&out[OFF_NH + go] = nh;
                }
            }
        }
    }
}

#define DSM_EX1 (3 * (2 * (128 * LDT * 2) + 2 * SAB_B))   // 122880
#define DSM_EX2 (3 * (2 * (64 * LDT * 2) + 2 * SAB_B))    // 92160
#define DSM_RTR (2 * (2 * (128 * LDT * 2) + 2 * SAB_B))   // 81920

// ---------------------------------------------------------------------------
// Router GEMM1 on HMMA (2-stage, proven).  Grid (2, 64, 5):
//   z=0: bundle router, A=[hnorm | sfe], B=br_W1^T, out=g_bh
//   z=1..4: intra router g=z-1, A=[hnorm | bemb_g], B=ir_W1^T[g], out=g_ih
// ---------------------------------------------------------------------------
__global__ void __launch_bounds__(256) router_mma(
    const float* __restrict__ br_b1, const float* __restrict__ ir_b1)
{
    extern __shared__ bf16 dsm[];
    const uint32_t sbase = smem_u32(dsm);
    const int tid = threadIdx.x;
    const int wid = tid >> 5, lane = tid & 31;
    constexpr int STB = 2 * (128 * LDT * 2) + 2 * SAB_B;   // 40960
    const int m0 = blockIdx.y * 128;
    const int nt0 = blockIdx.x * 128;
    const int z = blockIdx.z;

    const bf16 *EAh, *EAl, *Bh, *Bl;
    const float* bias;
    float* ob;
    int lda2, out_ld, ocol;
    if (z == 0) {
        EAh = g_sfe_h; EAl = g_sfe_l; lda2 = DFE;
        Bh = g_wbr_h + (size_t)nt0 * RIN; Bl = g_wbr_l + (size_t)nt0 * RIN;
        bias = br_b1 + nt0;
        ob = g_bh; out_ld = DRH; ocol = nt0;
    } else {
        const int g = z - 1;
        EAh = g_bemb_h + g * DFE; EAl = g_bemb_l + g * DFE; lda2 = NB * DFE;
        Bh = g_wir_h + ((size_t)g * DRH + nt0) * RIN;
        Bl = g_wir_l + ((size_t)g * DRH + nt0) * RIN;
        bias = ir_b1 + g * DRH + nt0;
        ob = g_ih; out_ld = NB * DRH; ocol = g * DRH + nt0;
    }

    const int mw = (wid >> 2) * 64;
    const int nw = (wid & 3) * 32;
    const int nchunk = RIN / 32;  // 36

    float acc[4][4][4];
#pragma unroll
    for (int a = 0; a < 4; a++)
#pragma unroll
        for (int b = 0; b < 4; b++)
#pragma unroll
            for (int c = 0; c < 4; c++) acc[a][b][c] = 0.f;

    auto load_rt = [&](int ci) {
        const int k0 = ci * 32;
        const bf16 *Ah, *Al;
        int lda;
        if (k0 < D_HID) {
            Ah = g_ah + (size_t)m0 * D_HID + k0;
            Al = g_al + (size_t)m0 * D_HID + k0;
            lda = D_HID;
        } else {
            Ah = EAh + (size_t)m0 * lda2 + (k0 - D_HID);
            Al = EAl + (size_t)m0 * lda2 + (k0 - D_HID);
            lda = lda2;
        }
        load_ab<4>(sbase + (ci & 1) * STB, Ah, Al, lda, Bh + k0, Bl + k0, RIN, tid);
    };

    load_rt(0);
    CP_COMMIT();
    for (int ci = 0; ci < nchunk; ci++) {
        if (ci + 1 < nchunk) {
            load_rt(ci + 1);
            CP_COMMIT();
            CP_WAIT1();
        } else {
            CP_WAIT0();
        }
        __syncthreads();
        chunk_mma<4>(acc, sbase + (ci & 1) * STB, mw, nw, lane);
        __syncthreads();
    }

    const int mfrag = mw + (lane >> 2);
    const int nfrag = nw + (lane & 3) * 2;
#pragma unroll
    for (int mi = 0; mi < 4; mi++) {
        const int r0 = m0 + mfrag + mi * 16;
#pragma unroll
        for (int nj = 0; nj < 4; nj++) {
            const int nl = nfrag + nj * 8;
            const float* c = acc[mi][nj];
            float b0 = bias[nl], b1v = bias[nl + 1];
            float2 o0, o1;
            o0.x = gelu_f(c[0] + b0);
            o0.y = gelu_f(c[1] + b1v);
            o1.x = gelu_f(c[2] + b0);
            o1.y = gelu_f(c[3] + b1v);
            *(float2*)&ob[(size_t)r0 * out_ld + ocol + nl]       = o0;
            *(float2*)&ob[(size_t)(r0 + 8) * out_ld + ocol + nl] = o1;
        }
    }
}

// ---------------------------------------------------------------------------
extern "C" void kernel_launch(void* const* d_in, const int* in_sizes, int n_in,
                              void* d_out, int out_size)
{
    const float* hidden  = (const float*)d_in[0];
    const float* feat    = (const float*)d_in[1];
    const float* ln_g    = (const float*)d_in[2];
    const float* ln_b    = (const float*)d_in[3];
    const float* stage_W = (const float*)d_in[4];
    const float* stage_b = (const float*)d_in[5];
    const float* bproj_W = (const float*)d_in[6];
    const float* bproj_b = (const float*)d_in[7];
    const float* br_W1   = (const float*)d_in[8];
    const float* br_b1   = (const float*)d_in[9];
    const float* br_W2   = (const float*)d_in[10];
    const float* br_b2   = (const float*)d_in[11];
    const float* ir_W1   = (const float*)d_in[12];
    const float* ir_b1   = (const float*)d_in[13];
    const float* ir_W2   = (const float*)d_in[14];
    const float* ir_b2   = (const float*)d_in[15];
    const float* ex_W1   = (const float*)d_in[16];
    const float* ex_b1   = (const float*)d_in[17];
    const float* ex_W2   = (const float*)d_in[18];
    const float* ex_b2   = (const float*)d_in[19];
    const float* alpha   = (const float*)d_in[20];
    float* out = (float*)d_out;

    cudaFuncSetAttribute((const void*)mma_kernel<1, 4>,
                         cudaFuncAttributeMaxDynamicSharedMemorySize, DSM_EX1);
    cudaFuncSetAttribute((const void*)mma_kernel<2, 2>,
                         cudaFuncAttributeMaxDynamicSharedMemorySize, DSM_EX2);
    cudaFuncSetAttribute((const void*)router_mma,
                         cudaFuncAttributeMaxDynamicSharedMemorySize, DSM_RTR);

    prep_kernel<<<M_TOK, 256>>>(hidden, feat, ln_g, ln_b,
                                stage_W, stage_b, bproj_W, bproj_b);
    {
        dim3 g(DEH / 32, D_HID / 32, NE);
        transpose_split<1><<<g, 256>>>(ex_W1);
    }
    {
        dim3 g(D_HID / 32, NEH / 32, 1);
        transpose_split<2><<<g, 256>>>(ex_W2);
    }
    {
        dim3 g(DRH / 32, RIN / 32, 1);
        transpose_split<3><<<g, 256>>>(br_W1);
    }
    {
        dim3 g(DRH / 32, RIN / 32, NB);
        transpose_split<4><<<g, 256>>>(ir_W1);
    }
    {
        dim3 g(DRH / 128, M_TOK / 128, 1 + NB);
        router_mma<<<g, 256, DSM_RTR>>>(br_b1, ir_b1);
    }
    gate_kernel<<<M_TOK, 128>>>(br_W2, br_b2, ir_W2, ir_b2, out);
    gbias_kernel<<<M_TOK, 256>>>(ex_b2);
    {
        dim3 g(NEH / 128, M_TOK / 128, 1);
        mma_kernel<1, 4><<<g, 256, DSM_EX1>>>(ex_b1, hidden, alpha, out);
    }
    {
        dim3 g(D_HID / 128, M_TOK / 64, 1);
        mma_kernel<2, 2><<<g, 256, DSM_EX2>>>(ex_b1, hidden, alpha, out);
    }
}

// round 11
// speedup vs baseline: 1.5083x; 1.5083x over previous
#include <cuda_runtime.h>
#include <cuda_bf16.h>
#include <cuda_fp16.h>
#include <cstdint>

#define M_TOK 8192
#define D_HID 1024
#define F_FEAT 64
#define DFE 128
#define RIN 1152
#define DRH 256
#define NB 4
#define FPB 16
#define ES 4
#define NE 16
#define DEH 512
#define NEH (NE * DEH)

#define OFF_NH 0
#define OFF_GW (M_TOK * D_HID)
#define OFF_GL (OFF_GW + M_TOK * NE)
#define OFF_BW (OFF_GL + M_TOK * NE)
#define OFF_BL (OFF_BW + M_TOK * NB)
#define OFF_SD (OFF_BL + M_TOK * NB)

typedef unsigned long long ull;
typedef __nv_bfloat16 bf16;
typedef __half fp16;

// ------------------------- scratch ------------------------------------------
__device__ float g_bh[M_TOK * DRH];
__device__ float g_ih[M_TOK * NB * DRH];
__device__ float g_gate[M_TOK * NE];
__device__ float g_gbias[M_TOK * D_HID];
// router path (bf16 3-term, proven)
__device__ bf16 g_ah[M_TOK * D_HID];
__device__ bf16 g_al[M_TOK * D_HID];
__device__ bf16 g_sfe_h[M_TOK * DFE];
__device__ bf16 g_sfe_l[M_TOK * DFE];
__device__ bf16 g_bemb_h[M_TOK * NB * DFE];
__device__ bf16 g_bemb_l[M_TOK * NB * DFE];
__device__ bf16 g_wbr_h[DRH * RIN];
__device__ bf16 g_wbr_l[DRH * RIN];
__device__ bf16 g_wir_h[NB * DRH * RIN];
__device__ bf16 g_wir_l[NB * DRH * RIN];
// expert path (fp16 2-term: A single, B hi/lo)
__device__ fp16 g_xh[M_TOK * D_HID];          // hnorm fp16
__device__ fp16 g_w1s_h[NEH * D_HID];         // ex_W1^T hi  [n][k]
__device__ fp16 g_w1s_l[NEH * D_HID];         // ex_W1^T lo
__device__ fp16 g_w2s_h[D_HID * NEH];         // ex_W2^T hi  [n][k]
__device__ fp16 g_w2s_l[D_HID * NEH];         // ex_W2^T lo
__device__ fp16 g_eh[(size_t)M_TOK * NEH];    // gate*gelu(..) fp16

// ------------------------- helpers ------------------------------------------
__device__ __forceinline__ float gelu_f(float x) {
    return 0.5f * x * (1.0f + erff(x * 0.70710678118654752440f));
}
__device__ __forceinline__ void split_bf16(float v, bf16& h, bf16& l) {
    h = __float2bfloat16(v);
    l = __float2bfloat16(v - __bfloat162float(h));
}
__device__ __forceinline__ void split_fp16(float v, fp16& h, fp16& l) {
    h = __float2half(v);
    l = __float2half(v - __half2float(h));
}
__device__ __forceinline__ uint32_t smem_u32(const void* p) {
    uint32_t a;
    asm("{ .reg .u64 t; cvta.to.shared.u64 t, %1; cvt.u32.u64 %0, t; }"
        : "=r"(a) : "l"(p));
    return a;
}
__device__ __forceinline__ void cpa16(uint32_t s, const void* g) {
    asm volatile("cp.async.cg.shared.global [%0], [%1], 16;" :: "r"(s), "l"(g));
}
#define CP_COMMIT() asm volatile("cp.async.commit_group;" ::: "memory")
#define CP_WAIT1()  asm volatile("cp.async.wait_group 1;" ::: "memory")
#define CP_WAIT0()  asm volatile("cp.async.wait_group 0;" ::: "memory")

__device__ __forceinline__ void ldsm4(uint32_t* r, uint32_t addr) {
    asm volatile("ldmatrix.sync.aligned.m8n8.x4.shared.b16 {%0,%1,%2,%3}, [%4];"
        : "=r"(r[0]), "=r"(r[1]), "=r"(r[2]), "=r"(r[3]) : "r"(addr));
}
__device__ __forceinline__ void mma_bf(float* c, const uint32_t* a, const uint32_t* b) {
    asm volatile("mma.sync.aligned.m16n8k16.row.col.f32.bf16.bf16.f32 "
        "{%0,%1,%2,%3}, {%4,%5,%6,%7}, {%8,%9}, {%0,%1,%2,%3};"
        : "+f"(c[0]), "+f"(c[1]), "+f"(c[2]), "+f"(c[3])
        : "r"(a[0]), "r"(a[1]), "r"(a[2]), "r"(a[3]), "r"(b[0]), "r"(b[1]));
}
__device__ __forceinline__ void mma_fp(float* c, const uint32_t* a, const uint32_t* b) {
    asm volatile("mma.sync.aligned.m16n8k16.row.col.f32.f16.f16.f32 "
        "{%0,%1,%2,%3}, {%4,%5,%6,%7}, {%8,%9}, {%0,%1,%2,%3};"
        : "+f"(c[0]), "+f"(c[1]), "+f"(c[2]), "+f"(c[3])
        : "r"(a[0]), "r"(a[1]), "r"(a[2]), "r"(a[3]), "r"(b[0]), "r"(b[1]));
}

// ---------------------------------------------------------------------------
// Kernel 1: LN (bf16 split for routers + fp16 for experts) + embeddings
// ---------------------------------------------------------------------------
__global__ void __launch_bounds__(256) prep_kernel(
    const float* __restrict__ hidden, const float* __restrict__ feat,
    const float* __restrict__ ln_g, const float* __restrict__ ln_b,
    const float* __restrict__ stage_W, const float* __restrict__ stage_b,
    const float* __restrict__ bproj_W, const float* __restrict__ bproj_b)
{
    const int t = blockIdx.x, tid = threadIdx.x;
    __shared__ float red[256];
    __shared__ float sfeat[F_FEAT];
    const float* hrow = hidden + (size_t)t * D_HID;
    float x[4], s = 0.f;
#pragma unroll
    for (int i = 0; i < 4; i++) { x[i] = hrow[tid + 256 * i]; s += x[i]; }
    if (tid < F_FEAT) sfeat[tid] = feat[(size_t)t * F_FEAT + tid];
    red[tid] = s;
    __syncthreads();
    for (int off = 128; off > 0; off >>= 1) {
        if (tid < off) red[tid] += red[tid + off];
        __syncthreads();
    }
    const float mu = red[0] * (1.0f / 1024.0f);
    __syncthreads();
    float v = 0.f;
#pragma unroll
    for (int i = 0; i < 4; i++) { float d = x[i] - mu; v += d * d; }
    red[tid] = v;
    __syncthreads();
    for (int off = 128; off > 0; off >>= 1) {
        if (tid < off) red[tid] += red[tid + off];
        __syncthreads();
    }
    const float rstd = rsqrtf(red[0] * (1.0f / 1024.0f) + 1e-5f);
#pragma unroll
    for (int i = 0; i < 4; i++) {
        int d = tid + 256 * i;
        float hv = (x[i] - mu) * rstd * ln_g[d] + ln_b[d];
        bf16 hi, lo; split_bf16(hv, hi, lo);
        g_ah[(size_t)t * D_HID + d] = hi;
        g_al[(size_t)t * D_HID + d] = lo;
        g_xh[(size_t)t * D_HID + d] = __float2half(hv);
    }
    if (tid < DFE) {
        float acc = stage_b[tid];
#pragma unroll
        for (int f = 0; f < F_FEAT; f++) acc += sfeat[f] * stage_W[f * DFE + tid];
        bf16 hi, lo; split_bf16(acc, hi, lo);
        g_sfe_h[(size_t)t * DFE + tid] = hi;
        g_sfe_l[(size_t)t * DFE + tid] = lo;
    }
    for (int idx = tid; idx < NB * DFE; idx += 256) {
        int g = idx >> 7, j = idx & 127;
        float acc = bproj_b[g * DFE + j];
#pragma unroll
        for (int f = 0; f < FPB; f++)
            acc += sfeat[g * FPB + f] * bproj_W[(g * FPB + f) * DFE + j];
        bf16 hi, lo; split_bf16(acc, hi, lo);
        g_bemb_h[(size_t)t * (NB * DFE) + idx] = hi;
        g_bemb_l[(size_t)t * (NB * DFE) + idx] = lo;
    }
}

// ---------------------------------------------------------------------------
// Transpose + split.
// W=1: ex_W1[z] (1024x512) -> w1s fp16;  W=2: ex_W2 flat (8192x1024) -> w2s fp16;
// W=3: br_W1 (1152x256) -> wbr bf16;     W=4: ir_W1[z] (1152x256) -> wir bf16.
// ---------------------------------------------------------------------------
template <int W>
__global__ void __launch_bounds__(256) transpose_split(const float* __restrict__ src)
{
    __shared__ float tl[32][33];
    const int z = blockIdx.z;
    const int C = (W == 1) ? DEH : ((W == 2) ? D_HID : DRH);
    const size_t dld = (W == 1) ? D_HID : ((W == 2) ? NEH : RIN);
    const size_t srcz = (W == 1) ? (size_t)D_HID * DEH : ((W == 4) ? (size_t)RIN * DRH : 0);
    const int dstz = (W == 1) ? DEH : ((W == 4) ? DRH : 0);
    const float* s = src + (size_t)z * srcz;
    const int r0 = blockIdx.y * 32, c0 = blockIdx.x * 32;
    const int tx = threadIdx.x & 31, ty = threadIdx.x >> 5;
#pragma unroll
    for (int i = 0; i < 4; i++)
        tl[ty + i * 8][tx] = s[(size_t)(r0 + ty + i * 8) * C + c0 + tx];
    __syncthreads();
#pragma unroll
    for (int i = 0; i < 4; i++) {
        int c = c0 + ty + i * 8;
        float v = tl[tx][ty + i * 8];
        size_t o = ((size_t)z * dstz + c) * dld + r0 + tx;
        if (W == 1) {
            fp16 hi, lo; split_fp16(v, hi, lo);
            g_w1s_h[o] = hi; g_w1s_l[o] = lo;
        } else if (W == 2) {
            fp16 hi, lo; split_fp16(v, hi, lo);
            g_w2s_h[o] = hi; g_w2s_l[o] = lo;
        } else if (W == 3) {
            bf16 hi, lo; split_bf16(v, hi, lo);
            g_wbr_h[o] = hi; g_wbr_l[o] = lo;
        } else {
            bf16 hi, lo; split_bf16(v, hi, lo);
            g_wir_h[o] = hi; g_wir_l[o] = lo;
        }
    }
}

// ---------------------------------------------------------------------------
// Gate kernel
// ---------------------------------------------------------------------------
__device__ __forceinline__ void top2sm4(const float* s, float* w) {
    float m1 = fmaxf(fmaxf(s[0], s[1]), fmaxf(s[2], s[3]));
    float m2 = -3.0e38f;
    bool used = false;
#pragma unroll
    for (int i = 0; i < 4; i++) {
        if (!used && s[i] == m1) used = true;
        else m2 = fmaxf(m2, s[i]);
    }
    float e[4], den = 0.f;
#pragma unroll
    for (int i = 0; i < 4; i++) {
        e[i] = (s[i] >= m2) ? expf(s[i] - m1) : 0.f;
        den += e[i];
    }
    float inv = 1.0f / den;
#pragma unroll
    for (int i = 0; i < 4; i++) w[i] = e[i] * inv;
}

__global__ void __launch_bounds__(128) gate_kernel(
    const float* __restrict__ br_W2, const float* __restrict__ br_b2,
    const float* __restrict__ ir_W2, const float* __restrict__ ir_b2,
    float* __restrict__ out)
{
    const int t = blockIdx.x, tid = threadIdx.x;
    __shared__ float sbh[DRH];
    __shared__ float sih[NB * DRH];
    __shared__ float slog[20];
    for (int i = tid; i < DRH; i += 128) sbh[i] = g_bh[(size_t)t * DRH + i];
    for (int i = tid; i < NB * DRH; i += 128) sih[i] = g_ih[(size_t)t * NB * DRH + i];
    __syncthreads();
    const int w = tid >> 5, lane = tid & 31;
    for (int d = w; d < 20; d += 4) {
        float s = 0.f;
        if (d < 4) {
            for (int k = lane; k < DRH; k += 32) s += sbh[k] * br_W2[k * NB + d];
        } else {
            int g = (d - 4) >> 2, e = (d - 4) & 3;
            const float* w2 = ir_W2 + g * DRH * ES;
            const float* ihg = sih + g * DRH;
            for (int k = lane; k < DRH; k += 32) s += ihg[k] * w2[k * ES + e];
        }
#pragma unroll
        for (int off = 16; off; off >>= 1) s += __shfl_xor_sync(0xffffffffu, s, off);
        if (lane == 0) slog[d] = s + ((d < 4) ? br_b2[d] : ir_b2[d - 4]);
    }
    __syncthreads();
    if (tid == 0) {
        float bl[4], bw[4], il[16], iw[16];
#pragma unroll
        for (int i = 0; i < 4; i++) bl[i] = slog[i];
#pragma unroll
        for (int i = 0; i < 16; i++) il[i] = slog[4 + i];
        top2sm4(bl, bw);
#pragma unroll
        for (int g = 0; g < 4; g++) top2sm4(&il[g * 4], &iw[g * 4]);
#pragma unroll
        for (int g = 0; g < 4; g++) {
            out[OFF_BW + (size_t)t * NB + g] = bw[g];
            out[OFF_BL + (size_t)t * NB + g] = bl[g];
#pragma unroll
            for (int e = 0; e < 4; e++) {
                int idx = g * 4 + e;
                float gw = bw[g] * iw[idx];
                out[OFF_GW + (size_t)t * NE + idx] = gw;
                out[OFF_GL + (size_t)t * NE + idx] = bl[g] + il[idx];
                g_gate[(size_t)t * NE + idx] = gw;
            }
        }
    }
}

// gbias[t,d] = sum_e gate[t,e] * ex_b2[e,d]
__global__ void __launch_bounds__(256) gbias_kernel(const float* __restrict__ ex_b2)
{
    const int t = blockIdx.x;
    __shared__ float sg[NE];
    if (threadIdx.x < NE) sg[threadIdx.x] = g_gate[(size_t)t * NE + threadIdx.x];
    __syncthreads();
    const int d = threadIdx.x * 4;
    float4 a = {0.f, 0.f, 0.f, 0.f};
#pragma unroll
    for (int e = 0; e < NE; e++) {
        float4 b = *(const float4*)&ex_b2[e * D_HID + d];
        a.x = fmaf(sg[e], b.x, a.x); a.y = fmaf(sg[e], b.y, a.y);
        a.z = fmaf(sg[e], b.z, a.z); a.w = fmaf(sg[e], b.w, a.w);
    }
    *(float4*)&g_gbias[(size_t)t * D_HID + d] = a;
}

// ---------------------------------------------------------------------------
// Common tile constants.  CTA 128x128, K-chunk 32, 8 warps (warp 64x32).
// ---------------------------------------------------------------------------
#define LDT 40                        // padded row (32 + 8 elems)
#define TILE_B 10240                  // one 128-row tile bytes: 128*LDT*2

// ======================= expert path (fp16, A + Bh + Bl) ====================
#define STB_E (3 * TILE_B)            // 30720
#define DSM_EX (2 * STB_E)            // 61440

__device__ __forceinline__ void load_e(
    uint32_t sbase, const fp16* __restrict__ A, int lda,
    const fp16* __restrict__ Bh, const fp16* __restrict__ Bl, int ldb, int tid)
{
#pragma unroll
    for (int i = 0; i < 2; i++) {
        int q = i * 256 + tid;
        int row = q >> 2, seg = q & 3;
        uint32_t so = (uint32_t)(row * LDT + seg * 8) * 2;
        cpa16(sbase + so,                A  + (size_t)row * lda + seg * 8);
        cpa16(sbase + TILE_B + so,       Bh + (size_t)row * ldb + seg * 8);
        cpa16(sbase + 2 * TILE_B + so,   Bl + (size_t)row * ldb + seg * 8);
    }
}

__device__ __forceinline__ void chunk_e(
    float (*acc)[4][4], uint32_t ab, int mw, int nw, int lane)
{
    const uint32_t bb = ab + TILE_B;
#pragma unroll
    for (int ks = 0; ks < 32; ks += 16) {
        uint32_t ah[4][4], bhf[2][4], blf[2][4];
#pragma unroll
        for (int mi = 0; mi < 4; mi++) {
            uint32_t ra = ab + (uint32_t)((mw + mi * 16 + (lane & 15)) * LDT
                                          + ks + ((lane >> 4) & 1) * 8) * 2;
            ldsm4(ah[mi], ra);
        }
#pragma unroll
        for (int pj = 0; pj < 2; pj++) {
            uint32_t rb = bb + (uint32_t)((nw + pj * 16 + ((lane >> 4) & 1) * 8
                                           + (lane & 7)) * LDT
                                          + ks + ((lane >> 3) & 1) * 8) * 2;
            ldsm4(bhf[pj], rb);
            ldsm4(blf[pj], rb + TILE_B);
        }
#pragma unroll
        for (int mi = 0; mi < 4; mi++)
#pragma unroll
            for (int nj = 0; nj < 4; nj++) {
                const int pj = nj >> 1, sb = (nj & 1) * 2;
                mma_fp(acc[mi][nj], ah[mi], &bhf[pj][sb]);
                mma_fp(acc[mi][nj], ah[mi], &blf[pj][sb]);
            }
    }
}

// EPI=1: ex1 (gelu(.+b1)*gate -> g_eh fp16).  EPI=2: ex2 (combine -> out).
template <int EPI>
__global__ void __launch_bounds__(256) mma_kernel(
    const float* __restrict__ b1, const float* __restrict__ hidden,
    const float* __restrict__ alpha_p, float* __restrict__ out)
{
    extern __shared__ fp16 dsm[];
    const uint32_t sbase = smem_u32(dsm);
    const int tid = threadIdx.x;
    const int wid = tid >> 5, lane = tid & 31;
    const int m0 = blockIdx.y * 128;
    const int n0 = blockIdx.x * 128;

    const int ldk = (EPI == 1) ? D_HID : NEH;
    const fp16* A  = ((EPI == 1) ? g_xh : g_eh) + (size_t)m0 * ldk;
    const fp16* Bh = ((EPI == 1) ? g_w1s_h : g_w2s_h) + (size_t)n0 * ldk;
    const fp16* Bl = ((EPI == 1) ? g_w1s_l : g_w2s_l) + (size_t)n0 * ldk;
    const int nchunk = ldk / 32;

    const int mw = (wid >> 2) * 64;
    const int nw = (wid & 3) * 32;

    float acc[4][4][4];
#pragma unroll
    for (int a = 0; a < 4; a++)
#pragma unroll
        for (int b = 0; b < 4; b++)
#pragma unroll
            for (int c = 0; c < 4; c++) acc[a][b][c] = 0.f;

    load_e(sbase, A, ldk, Bh, Bl, ldk, tid);
    CP_COMMIT();

    for (int ci = 0; ci < nchunk; ci++) {
        if (ci + 1 < nchunk) {
            load_e(sbase + ((ci + 1) & 1) * STB_E,
                   A + (ci + 1) * 32, ldk, Bh + (ci + 1) * 32, Bl + (ci + 1) * 32, ldk, tid);
            CP_COMMIT();
            CP_WAIT1();
        } else {
            CP_WAIT0();
        }
        __syncthreads();
        chunk_e(acc, sbase + (ci & 1) * STB_E, mw, nw, lane);
        __syncthreads();
    }

    const int mfrag = mw + (lane >> 2);
    const int nfrag = nw + (lane & 3) * 2;

    if (EPI == 1) {
        const int e = n0 >> 9;
#pragma unroll
        for (int mi = 0; mi < 4; mi++) {
            const int r0 = m0 + mfrag + mi * 16;
            const float gv0 = g_gate[(size_t)r0 * NE + e];
            const float gv1 = g_gate[(size_t)(r0 + 8) * NE + e];
#pragma unroll
            for (int nj = 0; nj < 4; nj++) {
                const int ng = n0 + nfrag + nj * 8;
                const float* c = acc[mi][nj];
                float o0 = gelu_f(c[0] + b1[ng])     * gv0;
                float o1 = gelu_f(c[1] + b1[ng + 1]) * gv0;
                float o2 = gelu_f(c[2] + b1[ng])     * gv1;
                float o3 = gelu_f(c[3] + b1[ng + 1]) * gv1;
                __half2 p0 = __floats2half2_rn(o0, o1);
                __half2 p1 = __floats2half2_rn(o2, o3);
                *(__half2*)&g_eh[(size_t)r0 * NEH + ng]       = p0;
                *(__half2*)&g_eh[(size_t)(r0 + 8) * NEH + ng] = p1;
            }
        }
    } else {
        const float alpha = *alpha_p;
#pragma unroll
        for (int mi = 0; mi < 4; mi++) {
            const int r0 = m0 + mfrag + mi * 16;
#pragma unroll
            for (int nj = 0; nj < 4; nj++) {
                const int ng = n0 + nfrag + nj * 8;
                const float* c = acc[mi][nj];
#pragma unroll
                for (int h = 0; h < 2; h++) {
                    const int r = r0 + h * 8;
                    const size_t go = (size_t)r * D_HID + ng;
                    float2 gb = *(const float2*)&g_gbias[go];
                    float2 hv = *(const float2*)&hidden[go];
                    float2 sd, nh;
                    sd.x = c[h * 2]     + gb.x;
                    sd.y = c[h * 2 + 1] + gb.y;
                    nh.x = hv.x + alpha * sd.x;
                    nh.y = hv.y + alpha * sd.y;
                    *(float2*)&out[OFF_SD + go] = sd;
                    *(float2*)&out[OFF_NH + go] = nh;
                }
            }
        }
    }
}

// ======================= router path (bf16 3-term, proven R9) ===============
#define STB_R (4 * TILE_B)            // Ah+Al+Bh+Bl = 40960
#define DSM_RTR (2 * STB_R)           // 81920

__device__ __forceinline__ void load_r(
    uint32_t sbase, const bf16* __restrict__ Ah, const bf16* __restrict__ Al, int lda,
    const bf16* __restrict__ Bh, const bf16* __restrict__ Bl, int ldb, int tid)
{
#pragma unroll
    for (int i = 0; i < 2; i++) {
        int q = i * 256 + tid;
        int row = q >> 2, seg = q & 3;
        uint32_t so = (uint32_t)(row * LDT + seg * 8) * 2;
        cpa16(sbase + so,               Ah + (size_t)row * lda + seg * 8);
        cpa16(sbase + TILE_B + so,      Al + (size_t)row * lda + seg * 8);
        cpa16(sbase + 2 * TILE_B + so,  Bh + (size_t)row * ldb + seg * 8);
        cpa16(sbase + 3 * TILE_B + so,  Bl + (size_t)row * ldb + seg * 8);
    }
}

__device__ __forceinline__ void chunk_r(
    float (*acc)[4][4], uint32_t ab, int mw, int nw, int lane)
{
    const uint32_t bb = ab + 2 * TILE_B;
#pragma unroll
    for (int ks = 0; ks < 32; ks += 16) {
        uint32_t ah[4][4], al[4][4], bhf[2][4], blf[2][4];
#pragma unroll
        for (int mi = 0; mi < 4; mi++) {
            uint32_t ra = ab + (uint32_t)((mw + mi * 16 + (lane & 15)) * LDT
                                          + ks + ((lane >> 4) & 1) * 8) * 2;
            ldsm4(ah[mi], ra);
            ldsm4(al[mi], ra + TILE_B);
        }
#pragma unroll
        for (int pj = 0; pj < 2; pj++) {
            uint32_t rb = bb + (uint32_t)((nw + pj * 16 + ((lane >> 4) & 1) * 8
                                           + (lane & 7)) * LDT
                                          + ks + ((lane >> 3) & 1) * 8) * 2;
            ldsm4(bhf[pj], rb);
            ldsm4(blf[pj], rb + TILE_B);
        }
#pragma unroll
        for (int mi = 0; mi < 4; mi++)
#pragma unroll
            for (int nj = 0; nj < 4; nj++) {
                const int pj = nj >> 1, sb = (nj & 1) * 2;
                mma_bf(acc[mi][nj], ah[mi], &bhf[pj][sb]);
                mma_bf(acc[mi][nj], ah[mi], &blf[pj][sb]);
                mma_bf(acc[mi][nj], al[mi], &bhf[pj][sb]);
            }
    }
}

// Grid (2, 64, 5): z=0 bundle router; z=1..4 intra router g=z-1.
__global__ void __launch_bounds__(256) router_mma(
    const float* __restrict__ br_b1, const float* __restrict__ ir_b1)
{
    extern __shared__ fp16 dsm[];
    const uint32_t sbase = smem_u32(dsm);
    const int tid = threadIdx.x;
    const int wid = tid >> 5, lane = tid & 31;
    const int m0 = blockIdx.y * 128;
    const int nt0 = blockIdx.x * 128;
    const int z = blockIdx.z;

    const bf16 *EAh, *EAl, *Bh, *Bl;
    const float* bias;
    float* ob;
    int lda2, out_ld, ocol;
    if (z == 0) {
        EAh = g_sfe_h; EAl = g_sfe_l; lda2 = DFE;
        Bh = g_wbr_h + (size_t)nt0 * RIN; Bl = g_wbr_l + (size_t)nt0 * RIN;
        bias = br_b1 + nt0;
        ob = g_bh; out_ld = DRH; ocol = nt0;
    } else {
        const int g = z - 1;
        EAh = g_bemb_h + g * DFE; EAl = g_bemb_l + g * DFE; lda2 = NB * DFE;
        Bh = g_wir_h + ((size_t)g * DRH + nt0) * RIN;
        Bl = g_wir_l + ((size_t)g * DRH + nt0) * RIN;
        bias = ir_b1 + g * DRH + nt0;
        ob = g_ih; out_ld = NB * DRH; ocol = g * DRH + nt0;
    }

    const int mw = (wid >> 2) * 64;
    const int nw = (wid & 3) * 32;
    const int nchunk = RIN / 32;  // 36

    float acc[4][4][4];
#pragma unroll
    for (int a = 0; a < 4; a++)
#pragma unroll
        for (int b = 0; b < 4; b++)
#pragma unroll
            for (int c = 0; c < 4; c++) acc[a][b][c] = 0.f;

    auto load_rt = [&](int ci) {
        const int k0 = ci * 32;
        const bf16 *Ah, *Al;
        int lda;
        if (k0 < D_HID) {
            Ah = g_ah + (size_t)m0 * D_HID + k0;
            Al = g_al + (size_t)m0 * D_HID + k0;
            lda = D_HID;
        } else {
            Ah = EAh + (size_t)m0 * lda2 + (k0 - D_HID);
            Al = EAl + (size_t)m0 * lda2 + (k0 - D_HID);
            lda = lda2;
        }
        load_r(sbase + (ci & 1) * STB_R, Ah, Al, lda, Bh + k0, Bl + k0, RIN, tid);
    };

    load_rt(0);
    CP_COMMIT();
    for (int ci = 0; ci < nchunk; ci++) {
        if (ci + 1 < nchunk) {
            load_rt(ci + 1);
            CP_COMMIT();
            CP_WAIT1();
        } else {
            CP_WAIT0();
        }
        __syncthreads();
        chunk_r(acc, sbase + (ci & 1) * STB_R, mw, nw, lane);
        __syncthreads();
    }

    const int mfrag = mw + (lane >> 2);
    const int nfrag = nw + (lane & 3) * 2;
#pragma unroll
    for (int mi = 0; mi < 4; mi++) {
        const int r0 = m0 + mfrag + mi * 16;
#pragma unroll
        for (int nj = 0; nj < 4; nj++) {
            const int nl = nfrag + nj * 8;
            const float* c = acc[mi][nj];
            float b0 = bias[nl], b1v = bias[nl + 1];
            float2 o0, o1;
            o0.x = gelu_f(c[0] + b0);
            o0.y = gelu_f(c[1] + b1v);
            o1.x = gelu_f(c[2] + b0);
            o1.y = gelu_f(c[3] + b1v);
            *(float2*)&ob[(size_t)r0 * out_ld + ocol + nl]       = o0;
            *(float2*)&ob[(size_t)(r0 + 8) * out_ld + ocol + nl] = o1;
        }
    }
}

// ---------------------------------------------------------------------------
extern "C" void kernel_launch(void* const* d_in, const int* in_sizes, int n_in,
                              void* d_out, int out_size)
{
    const float* hidden  = (const float*)d_in[0];
    const float* feat    = (const float*)d_in[1];
    const float* ln_g    = (const float*)d_in[2];
    const float* ln_b    = (const float*)d_in[3];
    const float* stage_W = (const float*)d_in[4];
    const float* stage_b = (const float*)d_in[5];
    const float* bproj_W = (const float*)d_in[6];
    const float* bproj_b = (const float*)d_in[7];
    const float* br_W1   = (const float*)d_in[8];
    const float* br_b1   = (const float*)d_in[9];
    const float* br_W2   = (const float*)d_in[10];
    const float* br_b2   = (const float*)d_in[11];
    const float* ir_W1   = (const float*)d_in[12];
    const float* ir_b1   = (const float*)d_in[13];
    const float* ir_W2   = (const float*)d_in[14];
    const float* ir_b2   = (const float*)d_in[15];
    const float* ex_W1   = (const float*)d_in[16];
    const float* ex_b1   = (const float*)d_in[17];
    const float* ex_W2   = (const float*)d_in[18];
    const float* ex_b2   = (const float*)d_in[19];
    const float* alpha   = (const float*)d_in[20];
    float* out = (float*)d_out;

    cudaFuncSetAttribute((const void*)mma_kernel<1>,
                         cudaFuncAttributeMaxDynamicSharedMemorySize, DSM_EX);
    cudaFuncSetAttribute((const void*)mma_kernel<2>,
                         cudaFuncAttributeMaxDynamicSharedMemorySize, DSM_EX);
    cudaFuncSetAttribute((const void*)router_mma,
                         cudaFuncAttributeMaxDynamicSharedMemorySize, DSM_RTR);

    prep_kernel<<<M_TOK, 256>>>(hidden, feat, ln_g, ln_b,
                                stage_W, stage_b, bproj_W, bproj_b);
    {
        dim3 g(DEH / 32, D_HID / 32, NE);
        transpose_split<1><<<g, 256>>>(ex_W1);
    }
    {
        dim3 g(D_HID / 32, NEH / 32, 1);
        transpose_split<2><<<g, 256>>>(ex_W2);
    }
    {
        dim3 g(DRH / 32, RIN / 32, 1);
        transpose_split<3><<<g, 256>>>(br_W1);
    }
    {
        dim3 g(DRH / 32, RIN / 32, NB);
        transpose_split<4><<<g, 256>>>(ir_W1);
    }
    {
        dim3 g(DRH / 128, M_TOK / 128, 1 + NB);
        router_mma<<<g, 256, DSM_RTR>>>(br_b1, ir_b1);
    }
    gate_kernel<<<M_TOK, 128>>>(br_W2, br_b2, ir_W2, ir_b2, out);
    gbias_kernel<<<M_TOK, 256>>>(ex_b2);
    {
        dim3 g(NEH / 128, M_TOK / 128, 1);
        mma_kernel<1><<<g, 256, DSM_EX>>>(ex_b1, hidden, alpha, out);
    }
    {
        dim3 g(D_HID / 128, M_TOK / 128, 1);
        mma_kernel<2><<<g, 256, DSM_EX>>>(ex_b1, hidden, alpha, out);
    }
}

// round 13
// speedup vs baseline: 3.6080x; 2.3921x over previous
#include <cuda_runtime.h>
#include <cuda_bf16.h>
#include <cuda_fp16.h>
#include <cstdint>

#define M_TOK 8192
#define D_HID 1024
#define F_FEAT 64
#define DFE 128
#define RIN 1152
#define DRH 256
#define NB 4
#define FPB 16
#define ES 4
#define NE 16
#define DEH 512
#define NEH (NE * DEH)

#define OFF_NH 0
#define OFF_GW (M_TOK * D_HID)
#define OFF_GL (OFF_GW + M_TOK * NE)
#define OFF_BW (OFF_GL + M_TOK * NE)
#define OFF_BL (OFF_BW + M_TOK * NB)
#define OFF_SD (OFF_BL + M_TOK * NB)

#define ECAP (M_TOK * 8)      // max dispatch entries (8 slots/token cap)
#define MAXTILES 1040

typedef unsigned long long ull;
typedef __nv_bfloat16 bf16;
typedef __half fp16;

// ------------------------- scratch ------------------------------------------
__device__ float g_bh[M_TOK * DRH];
__device__ float g_ih[M_TOK * NB * DRH];
__device__ float g_gate[M_TOK * NE];
// router path (bf16 3-term, proven)
__device__ bf16 g_ah[M_TOK * D_HID];
__device__ bf16 g_al[M_TOK * D_HID];
__device__ bf16 g_sfe_h[M_TOK * DFE];
__device__ bf16 g_sfe_l[M_TOK * DFE];
__device__ bf16 g_bemb_h[M_TOK * NB * DFE];
__device__ bf16 g_bemb_l[M_TOK * NB * DFE];
__device__ bf16 g_wbr_h[DRH * RIN];
__device__ bf16 g_wbr_l[DRH * RIN];
__device__ bf16 g_wir_h[NB * DRH * RIN];
__device__ bf16 g_wir_l[NB * DRH * RIN];
// expert path (fp16 2-term: A single, B hi/lo)
__device__ fp16 g_xh[M_TOK * D_HID];          // hnorm fp16
__device__ fp16 g_w1s_h[NEH * D_HID];         // ex_W1^T hi  [n][k]
__device__ fp16 g_w1s_l[NEH * D_HID];
__device__ fp16 g_w2s_h[D_HID * NEH];         // ex_W2^T hi  [n][k]
__device__ fp16 g_w2s_l[D_HID * NEH];
// sparse dispatch
__device__ int g_cnt[NE];
__device__ int g_off[NE + 1];
__device__ int g_list[NE * M_TOK];            // token ids per expert
__device__ int g_te[M_TOK * 8];               // per-token slot -> expert
__device__ int g_tp[M_TOK * 8];               // per-token slot -> pos in list
__device__ int g_tcnt[M_TOK];
__device__ int g_tile_e[MAXTILES];
__device__ int g_tile_m[MAXTILES];
__device__ int g_ntiles;
__device__ fp16 g_ehc[(size_t)(ECAP + 128) * DEH];    // compact gate*gelu
__device__ float g_eo[(size_t)(ECAP + 128) * D_HID];  // compact expert outputs

// ------------------------- helpers ------------------------------------------
__device__ __forceinline__ float gelu_f(float x) {
    return 0.5f * x * (1.0f + erff(x * 0.70710678118654752440f));
}
__device__ __forceinline__ void split_bf16(float v, bf16& h, bf16& l) {
    h = __float2bfloat16(v);
    l = __float2bfloat16(v - __bfloat162float(h));
}
__device__ __forceinline__ void split_fp16(float v, fp16& h, fp16& l) {
    h = __float2half(v);
    l = __float2half(v - __half2float(h));
}
__device__ __forceinline__ uint32_t smem_u32(const void* p) {
    uint32_t a;
    asm("{ .reg .u64 t; cvta.to.shared.u64 t, %1; cvt.u32.u64 %0, t; }"
        : "=r"(a) : "l"(p));
    return a;
}
__device__ __forceinline__ void cpa16(uint32_t s, const void* g) {
    asm volatile("cp.async.cg.shared.global [%0], [%1], 16;" :: "r"(s), "l"(g));
}
#define CP_COMMIT() asm volatile("cp.async.commit_group;" ::: "memory")
#define CP_WAIT1()  asm volatile("cp.async.wait_group 1;" ::: "memory")
#define CP_WAIT0()  asm volatile("cp.async.wait_group 0;" ::: "memory")

__device__ __forceinline__ void ldsm4(uint32_t* r, uint32_t addr) {
    asm volatile("ldmatrix.sync.aligned.m8n8.x4.shared.b16 {%0,%1,%2,%3}, [%4];"
        : "=r"(r[0]), "=r"(r[1]), "=r"(r[2]), "=r"(r[3]) : "r"(addr));
}
__device__ __forceinline__ void mma_bf(float* c, const uint32_t* a, const uint32_t* b) {
    asm volatile("mma.sync.aligned.m16n8k16.row.col.f32.bf16.bf16.f32 "
        "{%0,%1,%2,%3}, {%4,%5,%6,%7}, {%8,%9}, {%0,%1,%2,%3};"
        : "+f"(c[0]), "+f"(c[1]), "+f"(c[2]), "+f"(c[3])
        : "r"(a[0]), "r"(a[1]), "r"(a[2]), "r"(a[3]), "r"(b[0]), "r"(b[1]));
}
__device__ __forceinline__ void mma_fp(float* c, const uint32_t* a, const uint32_t* b) {
    asm volatile("mma.sync.aligned.m16n8k16.row.col.f32.f16.f16.f32 "
        "{%0,%1,%2,%3}, {%4,%5,%6,%7}, {%8,%9}, {%0,%1,%2,%3};"
        : "+f"(c[0]), "+f"(c[1]), "+f"(c[2]), "+f"(c[3])
        : "r"(a[0]), "r"(a[1]), "r"(a[2]), "r"(a[3]), "r"(b[0]), "r"(b[1]));
}

// ---------------------------------------------------------------------------
// Kernel 1: LN (bf16 split for routers + fp16 for experts) + embeddings
// ---------------------------------------------------------------------------
__global__ void __launch_bounds__(256) prep_kernel(
    const float* __restrict__ hidden, const float* __restrict__ feat,
    const float* __restrict__ ln_g, const float* __restrict__ ln_b,
    const float* __restrict__ stage_W, const float* __restrict__ stage_b,
    const float* __restrict__ bproj_W, const float* __restrict__ bproj_b)
{
    const int t = blockIdx.x, tid = threadIdx.x;
    __shared__ float red[256];
    __shared__ float sfeat[F_FEAT];
    const float* hrow = hidden + (size_t)t * D_HID;
    float x[4], s = 0.f;
#pragma unroll
    for (int i = 0; i < 4; i++) { x[i] = hrow[tid + 256 * i]; s += x[i]; }
    if (tid < F_FEAT) sfeat[tid] = feat[(size_t)t * F_FEAT + tid];
    red[tid] = s;
    __syncthreads();
    for (int off = 128; off > 0; off >>= 1) {
        if (tid < off) red[tid] += red[tid + off];
        __syncthreads();
    }
    const float mu = red[0] * (1.0f / 1024.0f);
    __syncthreads();
    float v = 0.f;
#pragma unroll
    for (int i = 0; i < 4; i++) { float d = x[i] - mu; v += d * d; }
    red[tid] = v;
    __syncthreads();
    for (int off = 128; off > 0; off >>= 1) {
        if (tid < off) red[tid] += red[tid + off];
        __syncthreads();
    }
    const float rstd = rsqrtf(red[0] * (1.0f / 1024.0f) + 1e-5f);
#pragma unroll
    for (int i = 0; i < 4; i++) {
        int d = tid + 256 * i;
        float hv = (x[i] - mu) * rstd * ln_g[d] + ln_b[d];
        bf16 hi, lo; split_bf16(hv, hi, lo);
        g_ah[(size_t)t * D_HID + d] = hi;
        g_al[(size_t)t * D_HID + d] = lo;
        g_xh[(size_t)t * D_HID + d] = __float2half(hv);
    }
    if (tid < DFE) {
        float acc = stage_b[tid];
#pragma unroll
        for (int f = 0; f < F_FEAT; f++) acc += sfeat[f] * stage_W[f * DFE + tid];
        bf16 hi, lo; split_bf16(acc, hi, lo);
        g_sfe_h[(size_t)t * DFE + tid] = hi;
        g_sfe_l[(size_t)t * DFE + tid] = lo;
    }
    for (int idx = tid; idx < NB * DFE; idx += 256) {
        int g = idx >> 7, j = idx & 127;
        float acc = bproj_b[g * DFE + j];
#pragma unroll
        for (int f = 0; f < FPB; f++)
            acc += sfeat[g * FPB + f] * bproj_W[(g * FPB + f) * DFE + j];
        bf16 hi, lo; split_bf16(acc, hi, lo);
        g_bemb_h[(size_t)t * (NB * DFE) + idx] = hi;
        g_bemb_l[(size_t)t * (NB * DFE) + idx] = lo;
    }
}

// ---------------------------------------------------------------------------
// Transpose + split (unchanged from R11)
// ---------------------------------------------------------------------------
template <int W>
__global__ void __launch_bounds__(256) transpose_split(const float* __restrict__ src)
{
    __shared__ float tl[32][33];
    const int z = blockIdx.z;
    const int C = (W == 1) ? DEH : ((W == 2) ? D_HID : DRH);
    const size_t dld = (W == 1) ? D_HID : ((W == 2) ? NEH : RIN);
    const size_t srcz = (W == 1) ? (size_t)D_HID * DEH : ((W == 4) ? (size_t)RIN * DRH : 0);
    const int dstz = (W == 1) ? DEH : ((W == 4) ? DRH : 0);
    const float* s = src + (size_t)z * srcz;
    const int r0 = blockIdx.y * 32, c0 = blockIdx.x * 32;
    const int tx = threadIdx.x & 31, ty = threadIdx.x >> 5;
#pragma unroll
    for (int i = 0; i < 4; i++)
        tl[ty + i * 8][tx] = s[(size_t)(r0 + ty + i * 8) * C + c0 + tx];
    __syncthreads();
#pragma unroll
    for (int i = 0; i < 4; i++) {
        int c = c0 + ty + i * 8;
        float v = tl[tx][ty + i * 8];
        size_t o = ((size_t)z * dstz + c) * dld + r0 + tx;
        if (W == 1) {
            fp16 hi, lo; split_fp16(v, hi, lo);
            g_w1s_h[o] = hi; g_w1s_l[o] = lo;
        } else if (W == 2) {
            fp16 hi, lo; split_fp16(v, hi, lo);
            g_w2s_h[o] = hi; g_w2s_l[o] = lo;
        } else if (W == 3) {
            bf16 hi, lo; split_bf16(v, hi, lo);
            g_wbr_h[o] = hi; g_wbr_l[o] = lo;
        } else {
            bf16 hi, lo; split_bf16(v, hi, lo);
            g_wir_h[o] = hi; g_wir_l[o] = lo;
        }
    }
}

// ---------------------------------------------------------------------------
// Gate kernel + dispatch list build
// ---------------------------------------------------------------------------
__device__ __forceinline__ void top2sm4(const float* s, float* w) {
    float m1 = fmaxf(fmaxf(s[0], s[1]), fmaxf(s[2], s[3]));
    float m2 = -3.0e38f;
    bool used = false;
#pragma unroll
    for (int i = 0; i < 4; i++) {
        if (!used && s[i] == m1) used = true;
        else m2 = fmaxf(m2, s[i]);
    }
    float e[4], den = 0.f;
#pragma unroll
    for (int i = 0; i < 4; i++) {
        e[i] = (s[i] >= m2) ? expf(s[i] - m1) : 0.f;
        den += e[i];
    }
    float inv = 1.0f / den;
#pragma unroll
    for (int i = 0; i < 4; i++) w[i] = e[i] * inv;
}

__global__ void zero_cnt_kernel() {
    if (threadIdx.x < NE) g_cnt[threadIdx.x] = 0;
}

__global__ void __launch_bounds__(128) gate_kernel(
    const float* __restrict__ br_W2, const float* __restrict__ br_b2,
    const float* __restrict__ ir_W2, const float* __restrict__ ir_b2,
    float* __restrict__ out)
{
    const int t = blockIdx.x, tid = threadIdx.x;
    __shared__ float sbh[DRH];
    __shared__ float sih[NB * DRH];
    __shared__ float slog[20];
    for (int i = tid; i < DRH; i += 128) sbh[i] = g_bh[(size_t)t * DRH + i];
    for (int i = tid; i < NB * DRH; i += 128) sih[i] = g_ih[(size_t)t * NB * DRH + i];
    __syncthreads();
    const int w = tid >> 5, lane = tid & 31;
    for (int d = w; d < 20; d += 4) {
        float s = 0.f;
        if (d < 4) {
            for (int k = lane; k < DRH; k += 32) s += sbh[k] * br_W2[k * NB + d];
        } else {
            int g = (d - 4) >> 2, e = (d - 4) & 3;
            const float* w2 = ir_W2 + g * DRH * ES;
            const float* ihg = sih + g * DRH;
            for (int k = lane; k < DRH; k += 32) s += ihg[k] * w2[k * ES + e];
        }
#pragma unroll
        for (int off = 16; off; off >>= 1) s += __shfl_xor_sync(0xffffffffu, s, off);
        if (lane == 0) slog[d] = s + ((d < 4) ? br_b2[d] : ir_b2[d - 4]);
    }
    __syncthreads();
    if (tid == 0) {
        float bl[4], bw[4], il[16], iw[16], gwv[16];
#pragma unroll
        for (int i = 0; i < 4; i++) bl[i] = slog[i];
#pragma unroll
        for (int i = 0; i < 16; i++) il[i] = slog[4 + i];
        top2sm4(bl, bw);
#pragma unroll
        for (int g = 0; g < 4; g++) top2sm4(&il[g * 4], &iw[g * 4]);
#pragma unroll
        for (int g = 0; g < 4; g++) {
            out[OFF_BW + (size_t)t * NB + g] = bw[g];
            out[OFF_BL + (size_t)t * NB + g] = bl[g];
#pragma unroll
            for (int e = 0; e < 4; e++) {
                int idx = g * 4 + e;
                float gw = bw[g] * iw[idx];
                gwv[idx] = gw;
                out[OFF_GW + (size_t)t * NE + idx] = gw;
                out[OFF_GL + (size_t)t * NE + idx] = bl[g] + il[idx];
                g_gate[(size_t)t * NE + idx] = gw;
            }
        }
        // dispatch lists
        int cnt = 0;
#pragma unroll
        for (int e = 0; e < NE; e++) {
            if (gwv[e] > 0.f) {
                int p = atomicAdd(&g_cnt[e], 1);
                g_list[e * M_TOK + p] = t;
                if (cnt < 8) { g_te[t * 8 + cnt] = e; g_tp[t * 8 + cnt] = p; }
                cnt++;
            }
        }
        g_tcnt[t] = cnt < 8 ? cnt : 8;
    }
}

// single-block scheduler: offsets + tile table
__global__ void sched_kernel() {
    if (threadIdx.x == 0) {
        int off = 0;
        for (int e = 0; e < NE; e++) { g_off[e] = off; off += g_cnt[e]; }
        g_off[NE] = off;
        int nt = 0;
        for (int e = 0; e < NE; e++) {
            int T = (g_cnt[e] + 127) >> 7;
            for (int m = 0; m < T && nt < MAXTILES; m++) {
                g_tile_e[nt] = e; g_tile_m[nt] = m; nt++;
            }
        }
        g_ntiles = nt;
    }
}

// ---------------------------------------------------------------------------
// Common tile constants.  CTA 128x128, K-chunk 32, 8 warps (warp 64x32).
// ---------------------------------------------------------------------------
#define LDT 40
#define TILE_B 10240
#define STB_E (3 * TILE_B)            // 30720
#define DSM_EX (2 * STB_E)            // 61440

__device__ __forceinline__ void load_e(
    uint32_t sbase, const fp16* __restrict__ A, int lda,
    const fp16* __restrict__ Bh, const fp16* __restrict__ Bl, int ldb, int tid)
{
#pragma unroll
    for (int i = 0; i < 2; i++) {
        int q = i * 256 + tid;
        int row = q >> 2, seg = q & 3;
        uint32_t so = (uint32_t)(row * LDT + seg * 8) * 2;
        cpa16(sbase + so,                A  + (size_t)row * lda + seg * 8);
        cpa16(sbase + TILE_B + so,       Bh + (size_t)row * ldb + seg * 8);
        cpa16(sbase + 2 * TILE_B + so,   Bl + (size_t)row * ldb + seg * 8);
    }
}

__device__ __forceinline__ void chunk_e(
    float (*acc)[4][4], uint32_t ab, int mw, int nw, int lane)
{
    const uint32_t bb = ab + TILE_B;
#pragma unroll
    for (int ks = 0; ks < 32; ks += 16) {
        uint32_t ah[4][4], bhf[2][4], blf[2][4];
#pragma unroll
        for (int mi = 0; mi < 4; mi++) {
            uint32_t ra = ab + (uint32_t)((mw + mi * 16 + (lane & 15)) * LDT
                                          + ks + ((lane >> 4) & 1) * 8) * 2;
            ldsm4(ah[mi], ra);
        }
#pragma unroll
        for (int pj = 0; pj < 2; pj++) {
            uint32_t rb = bb + (uint32_t)((nw + pj * 16 + ((lane >> 4) & 1) * 8
                                           + (lane & 7)) * LDT
                                          + ks + ((lane >> 3) & 1) * 8) * 2;
            ldsm4(bhf[pj], rb);
            ldsm4(blf[pj], rb + TILE_B);
        }
#pragma unroll
        for (int mi = 0; mi < 4; mi++)
#pragma unroll
            for (int nj = 0; nj < 4; nj++) {
                const int pj = nj >> 1, sb = (nj & 1) * 2;
                mma_fp(acc[mi][nj], ah[mi], &bhf[pj][sb]);
                mma_fp(acc[mi][nj], ah[mi], &blf[pj][sb]);
            }
    }
}

// ---------------------------------------------------------------------------
// ex1 grouped GEMM: gathered tokens x W1[e] -> compact ehc (gate*gelu, fp16)
// grid (4, MAXTILES)
// ---------------------------------------------------------------------------
__global__ void __launch_bounds__(256) ex1_kernel(const float* __restrict__ ex_b1)
{
    extern __shared__ fp16 dsm[];
    __shared__ int stok[128];
    const uint32_t sbase = smem_u32(dsm);
    const int tid = threadIdx.x;
    const int wid = tid >> 5, lane = tid & 31;
    if (blockIdx.y >= g_ntiles) return;
    const int e = g_tile_e[blockIdx.y], mt = g_tile_m[blockIdx.y];
    const int cnt = g_cnt[e], off = g_off[e];
    const int base = mt * 128;
    if (tid < 128) {
        int idx = base + tid;
        stok[tid] = g_list[e * M_TOK + (idx < cnt ? idx : cnt - 1)];
    }
    __syncthreads();
    const int n0 = blockIdx.x * 128;
    const fp16* Bh = g_w1s_h + (size_t)(e * DEH + n0) * D_HID;
    const fp16* Bl = g_w1s_l + (size_t)(e * DEH + n0) * D_HID;

    const int mw = (wid >> 2) * 64;
    const int nw = (wid & 3) * 32;

    float acc[4][4][4];
#pragma unroll
    for (int a = 0; a < 4; a++)
#pragma unroll
        for (int b = 0; b < 4; b++)
#pragma unroll
            for (int c = 0; c < 4; c++) acc[a][b][c] = 0.f;

    auto load1 = [&](int ci) {
        const uint32_t sb = sbase + (ci & 1) * STB_E;
        const int k0 = ci * 32;
#pragma unroll
        for (int i = 0; i < 2; i++) {
            int q = i * 256 + tid;
            int row = q >> 2, seg = q & 3;
            uint32_t so = (uint32_t)(row * LDT + seg * 8) * 2;
            cpa16(sb + so, g_xh + (size_t)stok[row] * D_HID + k0 + seg * 8);
            cpa16(sb + TILE_B + so,     Bh + (size_t)row * D_HID + k0 + seg * 8);
            cpa16(sb + 2 * TILE_B + so, Bl + (size_t)row * D_HID + k0 + seg * 8);
        }
    };

    const int nchunk = D_HID / 32;   // 32
    load1(0);
    CP_COMMIT();
    for (int ci = 0; ci < nchunk; ci++) {
        if (ci + 1 < nchunk) { load1(ci + 1); CP_COMMIT(); CP_WAIT1(); }
        else                 { CP_WAIT0(); }
        __syncthreads();
        chunk_e(acc, sbase + (ci & 1) * STB_E, mw, nw, lane);
        __syncthreads();
    }

    const int mfrag = mw + (lane >> 2);
    const int nfrag = nw + (lane & 3) * 2;
#pragma unroll
    for (int mi = 0; mi < 4; mi++) {
        const int r0 = mfrag + mi * 16;
#pragma unroll
        for (int h = 0; h < 2; h++) {
            const int r = r0 + h * 8;
            if (base + r >= cnt) continue;
            const int t = stok[r];
            const float gv = g_gate[(size_t)t * NE + e];
#pragma unroll
            for (int nj = 0; nj < 4; nj++) {
                const int nl = nfrag + nj * 8;
                const float* c = acc[mi][nj];
                float o0 = gelu_f(c[h * 2]     + ex_b1[e * DEH + n0 + nl])     * gv;
                float o1 = gelu_f(c[h * 2 + 1] + ex_b1[e * DEH + n0 + nl + 1]) * gv;
                *(__half2*)&g_ehc[(size_t)(off + base + r) * DEH + n0 + nl] =
                    __floats2half2_rn(o0, o1);
            }
        }
    }
}

// ---------------------------------------------------------------------------
// ex2 grouped GEMM: compact ehc x W2[e] -> compact eo (f32)
// grid (8, MAXTILES)
// ---------------------------------------------------------------------------
__global__ void __launch_bounds__(256) ex2_kernel()
{
    extern __shared__ fp16 dsm[];
    const uint32_t sbase = smem_u32(dsm);
    const int tid = threadIdx.x;
    const int wid = tid >> 5, lane = tid & 31;
    if (blockIdx.y >= g_ntiles) return;
    const int e = g_tile_e[blockIdx.y], mt = g_tile_m[blockIdx.y];
    const int cnt = g_cnt[e], off = g_off[e];
    const int base = mt * 128;
    const int n0 = blockIdx.x * 128;

    const fp16* A  = g_ehc + (size_t)(off + base) * DEH;
    const fp16* Bh = g_w2s_h + (size_t)n0 * NEH + e * DEH;
    const fp16* Bl = g_w2s_l + (size_t)n0 * NEH + e * DEH;

    const int mw = (wid >> 2) * 64;
    const int nw = (wid & 3) * 32;

    float acc[4][4][4];
#pragma unroll
    for (int a = 0; a < 4; a++)
#pragma unroll
        for (int b = 0; b < 4; b++)
#pragma unroll
            for (int c = 0; c < 4; c++) acc[a][b][c] = 0.f;

    const int nchunk = DEH / 32;   // 16
    load_e(sbase, A, DEH, Bh, Bl, NEH, tid);
    CP_COMMIT();
    for (int ci = 0; ci < nchunk; ci++) {
        if (ci + 1 < nchunk) {
            load_e(sbase + ((ci + 1) & 1) * STB_E,
                   A + (ci + 1) * 32, DEH,
                   Bh + (ci + 1) * 32, Bl + (ci + 1) * 32, NEH, tid);
            CP_COMMIT(); CP_WAIT1();
        } else {
            CP_WAIT0();
        }
        __syncthreads();
        chunk_e(acc, sbase + (ci & 1) * STB_E, mw, nw, lane);
        __syncthreads();
    }

    const int mfrag = mw + (lane >> 2);
    const int nfrag = nw + (lane & 3) * 2;
#pragma unroll
    for (int mi = 0; mi < 4; mi++) {
        const int r0 = mfrag + mi * 16;
#pragma unroll
        for (int h = 0; h < 2; h++) {
            const int r = r0 + h * 8;
            if (base + r >= cnt) continue;
            const size_t go = (size_t)(off + base + r) * D_HID + n0;
#pragma unroll
            for (int nj = 0; nj < 4; nj++) {
                const int nl = nfrag + nj * 8;
                const float* c = acc[mi][nj];
                float2 v; v.x = c[h * 2]; v.y = c[h * 2 + 1];
                *(float2*)&g_eo[go + nl] = v;
            }
        }
    }
}

// ---------------------------------------------------------------------------
// combine: delta[t] = sum_s eo[entry(t,s)] + sum_s gate*b2[e_s]; write SD, NH
// ---------------------------------------------------------------------------
__global__ void __launch_bounds__(256) combine_kernel(
    const float* __restrict__ hidden, const float* __restrict__ ex_b2,
    const float* __restrict__ alpha_p, float* __restrict__ out)
{
    const int t = blockIdx.x, tid = threadIdx.x;
    __shared__ int se[8], sp[8];
    __shared__ int scnt_s;
    if (tid < 8) { se[tid] = g_te[t * 8 + tid]; sp[tid] = g_tp[t * 8 + tid]; }
    if (tid == 0) scnt_s = g_tcnt[t];
    __syncthreads();
    const int scnt = scnt_s;
    const int d = tid * 4;
    float4 acc = {0.f, 0.f, 0.f, 0.f};
    for (int s = 0; s < scnt; s++) {
        const int e = se[s];
        const size_t entry = (size_t)g_off[e] + sp[s];
        float4 v = *(const float4*)&g_eo[entry * D_HID + d];
        const float gw = g_gate[(size_t)t * NE + e];
        float4 b = *(const float4*)&ex_b2[e * D_HID + d];
        acc.x += v.x + gw * b.x; acc.y += v.y + gw * b.y;
        acc.z += v.z + gw * b.z; acc.w += v.w + gw * b.w;
    }
    const float alpha = *alpha_p;
    float4 h = *(const float4*)&hidden[(size_t)t * D_HID + d];
    float4 nh;
    nh.x = h.x + alpha * acc.x; nh.y = h.y + alpha * acc.y;
    nh.z = h.z + alpha * acc.z; nh.w = h.w + alpha * acc.w;
    *(float4*)&out[OFF_SD + (size_t)t * D_HID + d] = acc;
    *(float4*)&out[OFF_NH + (size_t)t * D_HID + d] = nh;
}

// ======================= router path (bf16 3-term, proven R9) ===============
#define STB_R (4 * TILE_B)
#define DSM_RTR (2 * STB_R)

__device__ __forceinline__ void load_r(
    uint32_t sbase, const bf16* __restrict__ Ah, const bf16* __restrict__ Al, int lda,
    const bf16* __restrict__ Bh, const bf16* __restrict__ Bl, int ldb, int tid)
{
#pragma unroll
    for (int i = 0; i < 2; i++) {
        int q = i * 256 + tid;
        int row = q >> 2, seg = q & 3;
        uint32_t so = (uint32_t)(row * LDT + seg * 8) * 2;
        cpa16(sbase + so,               Ah + (size_t)row * lda + seg * 8);
        cpa16(sbase + TILE_B + so,      Al + (size_t)row * lda + seg * 8);
        cpa16(sbase + 2 * TILE_B + so,  Bh + (size_t)row * ldb + seg * 8);
        cpa16(sbase + 3 * TILE_B + so,  Bl + (size_t)row * ldb + seg * 8);
    }
}

__device__ __forceinline__ void chunk_r(
    float (*acc)[4][4], uint32_t ab, int mw, int nw, int lane)
{
    const uint32_t bb = ab + 2 * TILE_B;
#pragma unroll
    for (int ks = 0; ks < 32; ks += 16) {
        uint32_t ah[4][4], al[4][4], bhf[2][4], blf[2][4];
#pragma unroll
        for (int mi = 0; mi < 4; mi++) {
            uint32_t ra = ab + (uint32_t)((mw + mi * 16 + (lane & 15)) * LDT
                                          + ks + ((lane >> 4) & 1) * 8) * 2;
            ldsm4(ah[mi], ra);
            ldsm4(al[mi], ra + TILE_B);
        }
#pragma unroll
        for (int pj = 0; pj < 2; pj++) {
            uint32_t rb = bb + (uint32_t)((nw + pj * 16 + ((lane >> 4) & 1) * 8
                                           + (lane & 7)) * LDT
                                          + ks + ((lane >> 3) & 1) * 8) * 2;
            ldsm4(bhf[pj], rb);
            ldsm4(blf[pj], rb + TILE_B);
        }
#pragma unroll
        for (int mi = 0; mi < 4; mi++)
#pragma unroll
            for (int nj = 0; nj < 4; nj++) {
                const int pj = nj >> 1, sb = (nj & 1) * 2;
                mma_bf(acc[mi][nj], ah[mi], &bhf[pj][sb]);
                mma_bf(acc[mi][nj], ah[mi], &blf[pj][sb]);
                mma_bf(acc[mi][nj], al[mi], &bhf[pj][sb]);
            }
    }
}

__global__ void __launch_bounds__(256) router_mma(
    const float* __restrict__ br_b1, const float* __restrict__ ir_b1)
{
    extern __shared__ fp16 dsm[];
    const uint32_t sbase = smem_u32(dsm);
    const int tid = threadIdx.x;
    const int wid = tid >> 5, lane = tid & 31;
    const int m0 = blockIdx.y * 128;
    const int nt0 = blockIdx.x * 128;
    const int z = blockIdx.z;

    const bf16 *EAh, *EAl, *Bh, *Bl;
    const float* bias;
    float* ob;
    int lda2, out_ld, ocol;
    if (z == 0) {
        EAh = g_sfe_h; EAl = g_sfe_l; lda2 = DFE;
        Bh = g_wbr_h + (size_t)nt0 * RIN; Bl = g_wbr_l + (size_t)nt0 * RIN;
        bias = br_b1 + nt0;
        ob = g_bh; out_ld = DRH; ocol = nt0;
    } else {
        const int g = z - 1;
        EAh = g_bemb_h + g * DFE; EAl = g_bemb_l + g * DFE; lda2 = NB * DFE;
        Bh = g_wir_h + ((size_t)g * DRH + nt0) * RIN;
        Bl = g_wir_l + ((size_t)g * DRH + nt0) * RIN;
        bias = ir_b1 + g * DRH + nt0;
        ob = g_ih; out_ld = NB * DRH; ocol = g * DRH + nt0;
    }

    const int mw = (wid >> 2) * 64;
    const int nw = (wid & 3) * 32;
    const int nchunk = RIN / 32;

    float acc[4][4][4];
#pragma unroll
    for (int a = 0; a < 4; a++)
#pragma unroll
        for (int b = 0; b < 4; b++)
#pragma unroll
            for (int c = 0; c < 4; c++) acc[a][b][c] = 0.f;

    auto load_rt = [&](int ci) {
        const int k0 = ci * 32;
        const bf16 *Ah, *Al;
        int lda;
        if (k0 < D_HID) {
            Ah = g_ah + (size_t)m0 * D_HID + k0;
            Al = g_al + (size_t)m0 * D_HID + k0;
            lda = D_HID;
        } else {
            Ah = EAh + (size_t)m0 * lda2 + (k0 - D_HID);
            Al = EAl + (size_t)m0 * lda2 + (k0 - D_HID);
            lda = lda2;
        }
        load_r(sbase + (ci & 1) * STB_R, Ah, Al, lda, Bh + k0, Bl + k0, RIN, tid);
    };

    load_rt(0);
    CP_COMMIT();
    for (int ci = 0; ci < nchunk; ci++) {
        if (ci + 1 < nchunk) { load_rt(ci + 1); CP_COMMIT(); CP_WAIT1(); }
        else                 { CP_WAIT0(); }
        __syncthreads();
        chunk_r(acc, sbase + (ci & 1) * STB_R, mw, nw, lane);
        __syncthreads();
    }

    const int mfrag = mw + (lane >> 2);
    const int nfrag = nw + (lane & 3) * 2;
#pragma unroll
    for (int mi = 0; mi < 4; mi++) {
        const int r0 = m0 + mfrag + mi * 16;
#pragma unroll
        for (int nj = 0; nj < 4; nj++) {
            const int nl = nfrag + nj * 8;
            const float* c = acc[mi][nj];
            float b0 = bias[nl], b1v = bias[nl + 1];
            float2 o0, o1;
            o0.x = gelu_f(c[0] + b0);
            o0.y = gelu_f(c[1] + b1v);
            o1.x = gelu_f(c[2] + b0);
            o1.y = gelu_f(c[3] + b1v);
            *(float2*)&ob[(size_t)r0 * out_ld + ocol + nl]       = o0;
            *(float2*)&ob[(size_t)(r0 + 8) * out_ld + ocol + nl] = o1;
        }
    }
}

// ---------------------------------------------------------------------------
extern "C" void kernel_launch(void* const* d_in, const int* in_sizes, int n_in,
                              void* d_out, int out_size)
{
    const float* hidden  = (const float*)d_in[0];
    const float* feat    = (const float*)d_in[1];
    const float* ln_g    = (const float*)d_in[2];
    const float* ln_b    = (const float*)d_in[3];
    const float* stage_W = (const float*)d_in[4];
    const float* stage_b = (const float*)d_in[5];
    const float* bproj_W = (const float*)d_in[6];
    const float* bproj_b = (const float*)d_in[7];
    const float* br_W1   = (const float*)d_in[8];
    const float* br_b1   = (const float*)d_in[9];
    const float* br_W2   = (const float*)d_in[10];
    const float* br_b2   = (const float*)d_in[11];
    const float* ir_W1   = (const float*)d_in[12];
    const float* ir_b1   = (const float*)d_in[13];
    const float* ir_W2   = (const float*)d_in[14];
    const float* ir_b2   = (const float*)d_in[15];
    const float* ex_W1   = (const float*)d_in[16];
    const float* ex_b1   = (const float*)d_in[17];
    const float* ex_W2   = (const float*)d_in[18];
    const float* ex_b2   = (const float*)d_in[19];
    const float* alpha   = (const float*)d_in[20];
    float* out = (float*)d_out;

    cudaFuncSetAttribute((const void*)ex1_kernel,
                         cudaFuncAttributeMaxDynamicSharedMemorySize, DSM_EX);
    cudaFuncSetAttribute((const void*)ex2_kernel,
                         cudaFuncAttributeMaxDynamicSharedMemorySize, DSM_EX);
    cudaFuncSetAttribute((const void*)router_mma,
                         cudaFuncAttributeMaxDynamicSharedMemorySize, DSM_RTR);

    prep_kernel<<<M_TOK, 256>>>(hidden, feat, ln_g, ln_b,
                                stage_W, stage_b, bproj_W, bproj_b);
    {
        dim3 g(DEH / 32, D_HID / 32, NE);
        transpose_split<1><<<g, 256>>>(ex_W1);
    }
    {
        dim3 g(D_HID / 32, NEH / 32, 1);
        transpose_split<2><<<g, 256>>>(ex_W2);
    }
    {
        dim3 g(DRH / 32, RIN / 32, 1);
        transpose_split<3><<<g, 256>>>(br_W1);
    }
    {
        dim3 g(DRH / 32, RIN / 32, NB);
        transpose_split<4><<<g, 256>>>(ir_W1);
    }
    {
        dim3 g(DRH / 128, M_TOK / 128, 1 + NB);
        router_mma<<<g, 256, DSM_RTR>>>(br_b1, ir_b1);
    }
    zero_cnt_kernel<<<1, 32>>>();
    gate_kernel<<<M_TOK, 128>>>(br_W2, br_b2, ir_W2, ir_b2, out);
    sched_kernel<<<1, 32>>>();
    {
        dim3 g(DEH / 128, MAXTILES, 1);
        ex1_kernel<<<g, 256, DSM_EX>>>(ex_b1);
    }
    {
        dim3 g(D_HID / 128, MAXTILES, 1);
        ex2_kernel<<<g, 256, DSM_EX>>>();
    }
    combine_kernel<<<M_TOK, 256>>>(hidden, ex_b2, alpha, out);
}

// round 16
// speedup vs baseline: 3.6604x; 1.0145x over previous
#include <cuda_runtime.h>
#include <cuda_bf16.h>
#include <cuda_fp16.h>
#include <cstdint>

#define M_TOK 8192
#define D_HID 1024
#define F_FEAT 64
#define DFE 128
#define RIN 1152
#define DRH 256
#define NB 4
#define FPB 16
#define ES 4
#define NE 16
#define DEH 512
#define NEH (NE * DEH)

#define OFF_NH 0
#define OFF_GW (M_TOK * D_HID)
#define OFF_GL (OFF_GW + M_TOK * NE)
#define OFF_BW (OFF_GL + M_TOK * NE)
#define OFF_BL (OFF_BW + M_TOK * NB)
#define OFF_SD (OFF_BL + M_TOK * NB)

#define ECAP (M_TOK * 8)      // max dispatch entries (8 slots/token cap)
#define MAXTILES 1040

typedef unsigned long long ull;
typedef __nv_bfloat16 bf16;
typedef __half fp16;

// ------------------------- scratch ------------------------------------------
__device__ float g_bh[M_TOK * DRH];
__device__ float g_ih[M_TOK * NB * DRH];
__device__ float g_gate[M_TOK * NE];
// router path (bf16 3-term, proven — routers are error-critical, keep precise)
__device__ bf16 g_ah[M_TOK * D_HID];
__device__ bf16 g_al[M_TOK * D_HID];
__device__ bf16 g_sfe_h[M_TOK * DFE];
__device__ bf16 g_sfe_l[M_TOK * DFE];
__device__ bf16 g_bemb_h[M_TOK * NB * DFE];
__device__ bf16 g_bemb_l[M_TOK * NB * DFE];
__device__ bf16 g_wbr_h[DRH * RIN];
__device__ bf16 g_wbr_l[DRH * RIN];
__device__ bf16 g_wir_h[NB * DRH * RIN];
__device__ bf16 g_wir_l[NB * DRH * RIN];
// expert path (fp16 2-term: A single, B hi/lo)
__device__ fp16 g_xh[M_TOK * D_HID];          // hnorm fp16
__device__ fp16 g_w1s_h[NEH * D_HID];         // ex_W1^T hi  [n][k]
__device__ fp16 g_w1s_l[NEH * D_HID];
__device__ fp16 g_w2s_h[D_HID * NEH];         // ex_W2^T hi  [n][k]
__device__ fp16 g_w2s_l[D_HID * NEH];
// sparse dispatch
__device__ int g_cnt[NE];
__device__ int g_off[NE + 1];
__device__ int g_list[NE * M_TOK];            // token ids per expert
__device__ int g_te[M_TOK * 8];               // per-token slot -> expert
__device__ int g_tp[M_TOK * 8];               // per-token slot -> pos in list
__device__ int g_tcnt[M_TOK];
__device__ int g_tile_e[MAXTILES];
__device__ int g_tile_m[MAXTILES];
__device__ int g_ntiles;
__device__ fp16 g_ehc[(size_t)(ECAP + 128) * DEH];    // compact gate*gelu
__device__ fp16 g_eo[(size_t)(ECAP + 128) * D_HID];   // compact expert outputs (fp16)

// ------------------------- helpers ------------------------------------------
__device__ __forceinline__ float gelu_f(float x) {
    return 0.5f * x * (1.0f + erff(x * 0.70710678118654752440f));
}
__device__ __forceinline__ void split_bf16(float v, bf16& h, bf16& l) {
    h = __float2bfloat16(v);
    l = __float2bfloat16(v - __bfloat162float(h));
}
__device__ __forceinline__ void split_fp16(float v, fp16& h, fp16& l) {
    h = __float2half(v);
    l = __float2half(v - __half2float(h));
}
__device__ __forceinline__ uint32_t smem_u32(const void* p) {
    uint32_t a;
    asm("{ .reg .u64 t; cvta.to.shared.u64 t, %1; cvt.u32.u64 %0, t; }"
        : "=r"(a) : "l"(p));
    return a;
}
__device__ __forceinline__ void cpa16(uint32_t s, const void* g) {
    asm volatile("cp.async.cg.shared.global [%0], [%1], 16;" :: "r"(s), "l"(g));
}
#define CP_COMMIT() asm volatile("cp.async.commit_group;" ::: "memory")
#define CP_WAIT1()  asm volatile("cp.async.wait_group 1;" ::: "memory")
#define CP_WAIT0()  asm volatile("cp.async.wait_group 0;" ::: "memory")

__device__ __forceinline__ void ldsm4(uint32_t* r, uint32_t addr) {
    asm volatile("ldmatrix.sync.aligned.m8n8.x4.shared.b16 {%0,%1,%2,%3}, [%4];"
        : "=r"(r[0]), "=r"(r[1]), "=r"(r[2]), "=r"(r[3]) : "r"(addr));
}
__device__ __forceinline__ void mma_bf(float* c, const uint32_t* a, const uint32_t* b) {
    asm volatile("mma.sync.aligned.m16n8k16.row.col.f32.bf16.bf16.f32 "
        "{%0,%1,%2,%3}, {%4,%5,%6,%7}, {%8,%9}, {%0,%1,%2,%3};"
        : "+f"(c[0]), "+f"(c[1]), "+f"(c[2]), "+f"(c[3])
        : "r"(a[0]), "r"(a[1]), "r"(a[2]), "r"(a[3]), "r"(b[0]), "r"(b[1]));
}
__device__ __forceinline__ void mma_fp(float* c, const uint32_t* a, const uint32_t* b) {
    asm volatile("mma.sync.aligned.m16n8k16.row.col.f32.f16.f16.f32 "
        "{%0,%1,%2,%3}, {%4,%5,%6,%7}, {%8,%9}, {%0,%1,%2,%3};"
        : "+f"(c[0]), "+f"(c[1]), "+f"(c[2]), "+f"(c[3])
        : "r"(a[0]), "r"(a[1]), "r"(a[2]), "r"(a[3]), "r"(b[0]), "r"(b[1]));
}

// ---------------------------------------------------------------------------
// Kernel 1: LN (bf16 split for routers + fp16 for experts) + embeddings
//           + dispatch-counter zeroing (block 0)
// ---------------------------------------------------------------------------
__global__ void __launch_bounds__(256) prep_kernel(
    const float* __restrict__ hidden, const float* __restrict__ feat,
    const float* __restrict__ ln_g, const float* __restrict__ ln_b,
    const float* __restrict__ stage_W, const float* __restrict__ stage_b,
    const float* __restrict__ bproj_W, const float* __restrict__ bproj_b)
{
    const int t = blockIdx.x, tid = threadIdx.x;
    if (t == 0 && tid < NE) g_cnt[tid] = 0;
    __shared__ float red[256];
    __shared__ float sfeat[F_FEAT];
    const float* hrow = hidden + (size_t)t * D_HID;
    float x[4], s = 0.f;
#pragma unroll
    for (int i = 0; i < 4; i++) { x[i] = hrow[tid + 256 * i]; s += x[i]; }
    if (tid < F_FEAT) sfeat[tid] = feat[(size_t)t * F_FEAT + tid];
    red[tid] = s;
    __syncthreads();
    for (int off = 128; off > 0; off >>= 1) {
        if (tid < off) red[tid] += red[tid + off];
        __syncthreads();
    }
    const float mu = red[0] * (1.0f / 1024.0f);
    __syncthreads();
    float v = 0.f;
#pragma unroll
    for (int i = 0; i < 4; i++) { float d = x[i] - mu; v += d * d; }
    red[tid] = v;
    __syncthreads();
    for (int off = 128; off > 0; off >>= 1) {
        if (tid < off) red[tid] += red[tid + off];
        __syncthreads();
    }
    const float rstd = rsqrtf(red[0] * (1.0f / 1024.0f) + 1e-5f);
#pragma unroll
    for (int i = 0; i < 4; i++) {
        int d = tid + 256 * i;
        float hv = (x[i] - mu) * rstd * ln_g[d] + ln_b[d];
        bf16 hi, lo; split_bf16(hv, hi, lo);
        g_ah[(size_t)t * D_HID + d] = hi;
        g_al[(size_t)t * D_HID + d] = lo;
        g_xh[(size_t)t * D_HID + d] = __float2half(hv);
    }
    if (tid < DFE) {
        float acc = stage_b[tid];
#pragma unroll
        for (int f = 0; f < F_FEAT; f++) acc += sfeat[f] * stage_W[f * DFE + tid];
        bf16 hi, lo; split_bf16(acc, hi, lo);
        g_sfe_h[(size_t)t * DFE + tid] = hi;
        g_sfe_l[(size_t)t * DFE + tid] = lo;
    }
    for (int idx = tid; idx < NB * DFE; idx += 256) {
        int g = idx >> 7, j = idx & 127;
        float acc = bproj_b[g * DFE + j];
#pragma unroll
        for (int f = 0; f < FPB; f++)
            acc += sfeat[g * FPB + f] * bproj_W[(g * FPB + f) * DFE + j];
        bf16 hi, lo; split_bf16(acc, hi, lo);
        g_bemb_h[(size_t)t * (NB * DFE) + idx] = hi;
        g_bemb_l[(size_t)t * (NB * DFE) + idx] = lo;
    }
}

// ---------------------------------------------------------------------------
// Transpose + split.
// W=1: ex_W1[z] -> w1s fp16;  W=2: ex_W2 flat -> w2s fp16;
// W=3: br_W1 -> wbr bf16;     W=4: ir_W1[z] -> wir bf16.
// ---------------------------------------------------------------------------
template <int W>
__global__ void __launch_bounds__(256) transpose_split(const float* __restrict__ src)
{
    __shared__ float tl[32][33];
    const int z = blockIdx.z;
    const int C = (W == 1) ? DEH : ((W == 2) ? D_HID : DRH);
    const size_t dld = (W == 1) ? D_HID : ((W == 2) ? NEH : RIN);
    const size_t srcz = (W == 1) ? (size_t)D_HID * DEH : ((W == 4) ? (size_t)RIN * DRH : 0);
    const int dstz = (W == 1) ? DEH : ((W == 4) ? DRH : 0);
    const float* s = src + (size_t)z * srcz;
    const int r0 = blockIdx.y * 32, c0 = blockIdx.x * 32;
    const int tx = threadIdx.x & 31, ty = threadIdx.x >> 5;
#pragma unroll
    for (int i = 0; i < 4; i++)
        tl[ty + i * 8][tx] = s[(size_t)(r0 + ty + i * 8) * C + c0 + tx];
    __syncthreads();
#pragma unroll
    for (int i = 0; i < 4; i++) {
        int c = c0 + ty + i * 8;
        float v = tl[tx][ty + i * 8];
        size_t o = ((size_t)z * dstz + c) * dld + r0 + tx;
        if (W == 1) {
            fp16 hi, lo; split_fp16(v, hi, lo);
            g_w1s_h[o] = hi; g_w1s_l[o] = lo;
        } else if (W == 2) {
            fp16 hi, lo; split_fp16(v, hi, lo);
            g_w2s_h[o] = hi; g_w2s_l[o] = lo;
        } else if (W == 3) {
            bf16 hi, lo; split_bf16(v, hi, lo);
            g_wbr_h[o] = hi; g_wbr_l[o] = lo;
        } else {
            bf16 hi, lo; split_bf16(v, hi, lo);
            g_wir_h[o] = hi; g_wir_l[o] = lo;
        }
    }
}

// ---------------------------------------------------------------------------
// Gate kernel + dispatch list build
// ---------------------------------------------------------------------------
__device__ __forceinline__ void top2sm4(const float* s, float* w) {
    float m1 = fmaxf(fmaxf(s[0], s[1]), fmaxf(s[2], s[3]));
    float m2 = -3.0e38f;
    bool used = false;
#pragma unroll
    for (int i = 0; i < 4; i++) {
        if (!used && s[i] == m1) used = true;
        else m2 = fmaxf(m2, s[i]);
    }
    float e[4], den = 0.f;
#pragma unroll
    for (int i = 0; i < 4; i++) {
        e[i] = (s[i] >= m2) ? expf(s[i] - m1) : 0.f;
        den += e[i];
    }
    float inv = 1.0f / den;
#pragma unroll
    for (int i = 0; i < 4; i++) w[i] = e[i] * inv;
}

__global__ void __launch_bounds__(128) gate_kernel(
    const float* __restrict__ br_W2, const float* __restrict__ br_b2,
    const float* __restrict__ ir_W2, const float* __restrict__ ir_b2,
    float* __restrict__ out)
{
    const int t = blockIdx.x, tid = threadIdx.x;
    __shared__ float sbh[DRH];
    __shared__ float sih[NB * DRH];
    __shared__ float slog[20];
    for (int i = tid; i < DRH; i += 128) sbh[i] = g_bh[(size_t)t * DRH + i];
    for (int i = tid; i < NB * DRH; i += 128) sih[i] = g_ih[(size_t)t * NB * DRH + i];
    __syncthreads();
    const int w = tid >> 5, lane = tid & 31;
    for (int d = w; d < 20; d += 4) {
        float s = 0.f;
        if (d < 4) {
            for (int k = lane; k < DRH; k += 32) s += sbh[k] * br_W2[k * NB + d];
        } else {
            int g = (d - 4) >> 2, e = (d - 4) & 3;
            const float* w2 = ir_W2 + g * DRH * ES;
            const float* ihg = sih + g * DRH;
            for (int k = lane; k < DRH; k += 32) s += ihg[k] * w2[k * ES + e];
        }
#pragma unroll
        for (int off = 16; off; off >>= 1) s += __shfl_xor_sync(0xffffffffu, s, off);
        if (lane == 0) slog[d] = s + ((d < 4) ? br_b2[d] : ir_b2[d - 4]);
    }
    __syncthreads();
    if (tid == 0) {
        float bl[4], bw[4], il[16], iw[16], gwv[16];
#pragma unroll
        for (int i = 0; i < 4; i++) bl[i] = slog[i];
#pragma unroll
        for (int i = 0; i < 16; i++) il[i] = slog[4 + i];
        top2sm4(bl, bw);
#pragma unroll
        for (int g = 0; g < 4; g++) top2sm4(&il[g * 4], &iw[g * 4]);
#pragma unroll
        for (int g = 0; g < 4; g++) {
            out[OFF_BW + (size_t)t * NB + g] = bw[g];
            out[OFF_BL + (size_t)t * NB + g] = bl[g];
#pragma unroll
            for (int e = 0; e < 4; e++) {
                int idx = g * 4 + e;
                float gw = bw[g] * iw[idx];
                gwv[idx] = gw;
                out[OFF_GW + (size_t)t * NE + idx] = gw;
                out[OFF_GL + (size_t)t * NE + idx] = bl[g] + il[idx];
                g_gate[(size_t)t * NE + idx] = gw;
            }
        }
        // dispatch lists
        int cnt = 0;
#pragma unroll
        for (int e = 0; e < NE; e++) {
            if (gwv[e] > 0.f) {
                int p = atomicAdd(&g_cnt[e], 1);
                g_list[e * M_TOK + p] = t;
                if (cnt < 8) { g_te[t * 8 + cnt] = e; g_tp[t * 8 + cnt] = p; }
                cnt++;
            }
        }
        g_tcnt[t] = cnt < 8 ? cnt : 8;
    }
}

// single-block scheduler: offsets + tile table
__global__ void sched_kernel() {
    if (threadIdx.x == 0) {
        int off = 0;
        for (int e = 0; e < NE; e++) { g_off[e] = off; off += g_cnt[e]; }
        g_off[NE] = off;
        int nt = 0;
        for (int e = 0; e < NE; e++) {
            int T = (g_cnt[e] + 127) >> 7;
            for (int m = 0; m < T && nt < MAXTILES; m++) {
                g_tile_e[nt] = e; g_tile_m[nt] = m; nt++;
            }
        }
        g_ntiles = nt;
    }
}

// ---------------------------------------------------------------------------
// Common tile constants.  CTA 128x128, K-chunk 32, 8 warps (warp 64x32).
// ---------------------------------------------------------------------------
#define LDT 40
#define TILE_B 10240
#define STB_E (3 * TILE_B)            // 30720
#define DSM_EX (2 * STB_E)            // 61440

__device__ __forceinline__ void load_e(
    uint32_t sbase, const fp16* __restrict__ A, int lda,
    const fp16* __restrict__ Bh, const fp16* __restrict__ Bl, int ldb, int tid)
{
#pragma unroll
    for (int i = 0; i < 2; i++) {
        int q = i * 256 + tid;
        int row = q >> 2, seg = q & 3;
        uint32_t so = (uint32_t)(row * LDT + seg * 8) * 2;
        cpa16(sbase + so,                A  + (size_t)row * lda + seg * 8);
        cpa16(sbase + TILE_B + so,       Bh + (size_t)row * ldb + seg * 8);
        cpa16(sbase + 2 * TILE_B + so,   Bl + (size_t)row * ldb + seg * 8);
    }
}

__device__ __forceinline__ void chunk_e(
    float (*acc)[4][4], uint32_t ab, int mw, int nw, int lane)
{
    const uint32_t bb = ab + TILE_B;
#pragma unroll
    for (int ks = 0; ks < 32; ks += 16) {
        uint32_t ah[4][4], bhf[2][4], blf[2][4];
#pragma unroll
        for (int mi = 0; mi < 4; mi++) {
            uint32_t ra = ab + (uint32_t)((mw + mi * 16 + (lane & 15)) * LDT
                                          + ks + ((lane >> 4) & 1) * 8) * 2;
            ldsm4(ah[mi], ra);
        }
#pragma unroll
        for (int pj = 0; pj < 2; pj++) {
            uint32_t rb = bb + (uint32_t)((nw + pj * 16 + ((lane >> 4) & 1) * 8
                                           + (lane & 7)) * LDT
                                          + ks + ((lane >> 3) & 1) * 8) * 2;
            ldsm4(bhf[pj], rb);
            ldsm4(blf[pj], rb + TILE_B);
        }
#pragma unroll
        for (int mi = 0; mi < 4; mi++)
#pragma unroll
            for (int nj = 0; nj < 4; nj++) {
                const int pj = nj >> 1, sb = (nj & 1) * 2;
                mma_fp(acc[mi][nj], ah[mi], &bhf[pj][sb]);
                mma_fp(acc[mi][nj], ah[mi], &blf[pj][sb]);
            }
    }
}

// ---------------------------------------------------------------------------
// ex1 grouped GEMM: gathered tokens x W1[e] -> compact ehc (gate*gelu, fp16)
// ---------------------------------------------------------------------------
__global__ void __launch_bounds__(256) ex1_kernel(const float* __restrict__ ex_b1)
{
    extern __shared__ fp16 dsm[];
    __shared__ int stok[128];
    const uint32_t sbase = smem_u32(dsm);
    const int tid = threadIdx.x;
    const int wid = tid >> 5, lane = tid & 31;
    if (blockIdx.y >= g_ntiles) return;
    const int e = g_tile_e[blockIdx.y], mt = g_tile_m[blockIdx.y];
    const int cnt = g_cnt[e], off = g_off[e];
    const int base = mt * 128;
    if (tid < 128) {
        int idx = base + tid;
        stok[tid] = g_list[e * M_TOK + (idx < cnt ? idx : cnt - 1)];
    }
    __syncthreads();
    const int n0 = blockIdx.x * 128;
    const fp16* Bh = g_w1s_h + (size_t)(e * DEH + n0) * D_HID;
    const fp16* Bl = g_w1s_l + (size_t)(e * DEH + n0) * D_HID;

    const int mw = (wid >> 2) * 64;
    const int nw = (wid & 3) * 32;

    float acc[4][4][4];
#pragma unroll
    for (int a = 0; a < 4; a++)
#pragma unroll
        for (int b = 0; b < 4; b++)
#pragma unroll
            for (int c = 0; c < 4; c++) acc[a][b][c] = 0.f;

    auto load1 = [&](int ci) {
        const uint32_t sb = sbase + (ci & 1) * STB_E;
        const int k0 = ci * 32;
#pragma unroll
        for (int i = 0; i < 2; i++) {
            int q = i * 256 + tid;
            int row = q >> 2, seg = q & 3;
            uint32_t so = (uint32_t)(row * LDT + seg * 8) * 2;
            cpa16(sb + so, g_xh + (size_t)stok[row] * D_HID + k0 + seg * 8);
            cpa16(sb + TILE_B + so,     Bh + (size_t)row * D_HID + k0 + seg * 8);
            cpa16(sb + 2 * TILE_B + so, Bl + (size_t)row * D_HID + k0 + seg * 8);
        }
    };

    const int nchunk = D_HID / 32;   // 32
    load1(0);
    CP_COMMIT();
    for (int ci = 0; ci < nchunk; ci++) {
        if (ci + 1 < nchunk) { load1(ci + 1); CP_COMMIT(); CP_WAIT1(); }
        else                 { CP_WAIT0(); }
        __syncthreads();
        chunk_e(acc, sbase + (ci & 1) * STB_E, mw, nw, lane);
        __syncthreads();
    }

    const int mfrag = mw + (lane >> 2);
    const int nfrag = nw + (lane & 3) * 2;
#pragma unroll
    for (int mi = 0; mi < 4; mi++) {
        const int r0 = mfrag + mi * 16;
#pragma unroll
        for (int h = 0; h < 2; h++) {
            const int r = r0 + h * 8;
            if (base + r >= cnt) continue;
            const int t = stok[r];
            const float gv = g_gate[(size_t)t * NE + e];
#pragma unroll
            for (int nj = 0; nj < 4; nj++) {
                const int nl = nfrag + nj * 8;
                const float* c = acc[mi][nj];
                float o0 = gelu_f(c[h * 2]     + ex_b1[e * DEH + n0 + nl])     * gv;
                float o1 = gelu_f(c[h * 2 + 1] + ex_b1[e * DEH + n0 + nl + 1]) * gv;
                *(__half2*)&g_ehc[(size_t)(off + base + r) * DEH + n0 + nl] =
                    __floats2half2_rn(o0, o1);
            }
        }
    }
}

// ---------------------------------------------------------------------------
// ex2 grouped GEMM: compact ehc x W2[e] -> compact eo (fp16)
// ---------------------------------------------------------------------------
__global__ void __launch_bounds__(256) ex2_kernel()
{
    extern __shared__ fp16 dsm[];
    const uint32_t sbase = smem_u32(dsm);
    const int tid = threadIdx.x;
    const int wid = tid >> 5, lane = tid & 31;
    if (blockIdx.y >= g_ntiles) return;
    const int e = g_tile_e[blockIdx.y], mt = g_tile_m[blockIdx.y];
    const int cnt = g_cnt[e], off = g_off[e];
    const int base = mt * 128;
    const int n0 = blockIdx.x * 128;

    const fp16* A  = g_ehc + (size_t)(off + base) * DEH;
    const fp16* Bh = g_w2s_h + (size_t)n0 * NEH + e * DEH;
    const fp16* Bl = g_w2s_l + (size_t)n0 * NEH + e * DEH;

    const int mw = (wid >> 2) * 64;
    const int nw = (wid & 3) * 32;

    float acc[4][4][4];
#pragma unroll
    for (int a = 0; a < 4; a++)
#pragma unroll
        for (int b = 0; b < 4; b++)
#pragma unroll
            for (int c = 0; c < 4; c++) acc[a][b][c] = 0.f;

    const int nchunk = DEH / 32;   // 16
    load_e(sbase, A, DEH, Bh, Bl, NEH, tid);
    CP_COMMIT();
    for (int ci = 0; ci < nchunk; ci++) {
        if (ci + 1 < nchunk) {
            load_e(sbase + ((ci + 1) & 1) * STB_E,
                   A + (ci + 1) * 32, DEH,
                   Bh + (ci + 1) * 32, Bl + (ci + 1) * 32, NEH, tid);
            CP_COMMIT(); CP_WAIT1();
        } else {
            CP_WAIT0();
        }
        __syncthreads();
        chunk_e(acc, sbase + (ci & 1) * STB_E, mw, nw, lane);
        __syncthreads();
    }

    const int mfrag = mw + (lane >> 2);
    const int nfrag = nw + (lane & 3) * 2;
#pragma unroll
    for (int mi = 0; mi < 4; mi++) {
        const int r0 = mfrag + mi * 16;
#pragma unroll
        for (int h = 0; h < 2; h++) {
            const int r = r0 + h * 8;
            if (base + r >= cnt) continue;
            const size_t go = (size_t)(off + base + r) * D_HID + n0;
#pragma unroll
            for (int nj = 0; nj < 4; nj++) {
                const int nl = nfrag + nj * 8;
                const float* c = acc[mi][nj];
                *(__half2*)&g_eo[go + nl] = __floats2half2_rn(c[h * 2], c[h * 2 + 1]);
            }
        }
    }
}

// ---------------------------------------------------------------------------
// combine: delta[t] = sum_s eo[entry(t,s)] + sum_s gate*b2[e_s]; write SD, NH
// ---------------------------------------------------------------------------
__global__ void __launch_bounds__(256) combine_kernel(
    const float* __restrict__ hidden, const float* __restrict__ ex_b2,
    const float* __restrict__ alpha_p, float* __restrict__ out)
{
    const int t = blockIdx.x, tid = threadIdx.x;
    __shared__ int se[8], sp[8];
    __shared__ int scnt_s;
    if (tid < 8) { se[tid] = g_te[t * 8 + tid]; sp[tid] = g_tp[t * 8 + tid]; }
    if (tid == 0) scnt_s = g_tcnt[t];
    __syncthreads();
    const int scnt = scnt_s;
    const int d = tid * 4;
    float4 acc = {0.f, 0.f, 0.f, 0.f};
    for (int s = 0; s < scnt; s++) {
        const int e = se[s];
        const size_t entry = (size_t)g_off[e] + sp[s];
        const __half2* p = (const __half2*)&g_eo[entry * D_HID + d];
        float2 v0 = __half22float2(p[0]);
        float2 v1 = __half22float2(p[1]);
        const float gw = g_gate[(size_t)t * NE + e];
        float4 b = *(const float4*)&ex_b2[e * D_HID + d];
        acc.x += v0.x + gw * b.x; acc.y += v0.y + gw * b.y;
        acc.z += v1.x + gw * b.z; acc.w += v1.y + gw * b.w;
    }
    const float alpha = *alpha_p;
    float4 h = *(const float4*)&hidden[(size_t)t * D_HID + d];
    float4 nh;
    nh.x = h.x + alpha * acc.x; nh.y = h.y + alpha * acc.y;
    nh.z = h.z + alpha * acc.z; nh.w = h.w + alpha * acc.w;
    *(float4*)&out[OFF_SD + (size_t)t * D_HID + d] = acc;
    *(float4*)&out[OFF_NH + (size_t)t * D_HID + d] = nh;
}

// ======================= router path (bf16 3-term, proven) ==================
#define STB_R (4 * TILE_B)
#define DSM_RTR (2 * STB_R)

__device__ __forceinline__ void load_r(
    uint32_t sbase, const bf16* __restrict__ Ah, const bf16* __restrict__ Al, int lda,
    const bf16* __restrict__ Bh, const bf16* __restrict__ Bl, int ldb, int tid)
{
#pragma unroll
    for (int i = 0; i < 2; i++) {
        int q = i * 256 + tid;
        int row = q >> 2, seg = q & 3;
        uint32_t so = (uint32_t)(row * LDT + seg * 8) * 2;
        cpa16(sbase + so,               Ah + (size_t)row * lda + seg * 8);
        cpa16(sbase + TILE_B + so,      Al + (size_t)row * lda + seg * 8);
        cpa16(sbase + 2 * TILE_B + so,  Bh + (size_t)row * ldb + seg * 8);
        cpa16(sbase + 3 * TILE_B + so,  Bl + (size_t)row * ldb + seg * 8);
    }
}

__device__ __forceinline__ void chunk_r(
    float (*acc)[4][4], uint32_t ab, int mw, int nw, int lane)
{
    const uint32_t bb = ab + 2 * TILE_B;
#pragma unroll
    for (int ks = 0; ks < 32; ks += 16) {
        uint32_t ah[4][4], al[4][4], bhf[2][4], blf[2][4];
#pragma unroll
        for (int mi = 0; mi < 4; mi++) {
            uint32_t ra = ab + (uint32_t)((mw + mi * 16 + (lane & 15)) * LDT
                                          + ks + ((lane >> 4) & 1) * 8) * 2;
            ldsm4(ah[mi], ra);
            ldsm4(al[mi], ra + TILE_B);
        }
#pragma unroll
        for (int pj = 0; pj < 2; pj++) {
            uint32_t rb = bb + (uint32_t)((nw + pj * 16 + ((lane >> 4) & 1) * 8
                                           + (lane & 7)) * LDT
                                          + ks + ((lane >> 3) & 1) * 8) * 2;
            ldsm4(bhf[pj], rb);
            ldsm4(blf[pj], rb + TILE_B);
        }
#pragma unroll
        for (int mi = 0; mi < 4; mi++)
#pragma unroll
            for (int nj = 0; nj < 4; nj++) {
                const int pj = nj >> 1, sb = (nj & 1) * 2;
                mma_bf(acc[mi][nj], ah[mi], &bhf[pj][sb]);
                mma_bf(acc[mi][nj], ah[mi], &blf[pj][sb]);
                mma_bf(acc[mi][nj], al[mi], &bhf[pj][sb]);
            }
    }
}

__global__ void __launch_bounds__(256) router_mma(
    const float* __restrict__ br_b1, const float* __restrict__ ir_b1)
{
    extern __shared__ fp16 dsm[];
    const uint32_t sbase = smem_u32(dsm);
    const int tid = threadIdx.x;
    const int wid = tid >> 5, lane = tid & 31;
    const int m0 = blockIdx.y * 128;
    const int nt0 = blockIdx.x * 128;
    const int z = blockIdx.z;

    const bf16 *EAh, *EAl, *Bh, *Bl;
    const float* bias;
    float* ob;
    int lda2, out_ld, ocol;
    if (z == 0) {
        EAh = g_sfe_h; EAl = g_sfe_l; lda2 = DFE;
        Bh = g_wbr_h + (size_t)nt0 * RIN; Bl = g_wbr_l + (size_t)nt0 * RIN;
        bias = br_b1 + nt0;
        ob = g_bh; out_ld = DRH; ocol = nt0;
    } else {
        const int g = z - 1;
        EAh = g_bemb_h + g * DFE; EAl = g_bemb_l + g * DFE; lda2 = NB * DFE;
        Bh = g_wir_h + ((size_t)g * DRH + nt0) * RIN;
        Bl = g_wir_l + ((size_t)g * DRH + nt0) * RIN;
        bias = ir_b1 + g * DRH + nt0;
        ob = g_ih; out_ld = NB * DRH; ocol = g * DRH + nt0;
    }

    const int mw = (wid >> 2) * 64;
    const int nw = (wid & 3) * 32;
    const int nchunk = RIN / 32;

    float acc[4][4][4];
#pragma unroll
    for (int a = 0; a < 4; a++)
#pragma unroll
        for (int b = 0; b < 4; b++)
#pragma unroll
            for (int c = 0; c < 4; c++) acc[a][b][c] = 0.f;

    auto load_rt = [&](int ci) {
        const int k0 = ci * 32;
        const bf16 *Ah, *Al;
        int lda;
        if (k0 < D_HID) {
            Ah = g_ah + (size_t)m0 * D_HID + k0;
            Al = g_al + (size_t)m0 * D_HID + k0;
            lda = D_HID;
        } else {
            Ah = EAh + (size_t)m0 * lda2 + (k0 - D_HID);
            Al = EAl + (size_t)m0 * lda2 + (k0 - D_HID);
            lda = lda2;
        }
        load_r(sbase + (ci & 1) * STB_R, Ah, Al, lda, Bh + k0, Bl + k0, RIN, tid);
    };

    load_rt(0);
    CP_COMMIT();
    for (int ci = 0; ci < nchunk; ci++) {
        if (ci + 1 < nchunk) { load_rt(ci + 1); CP_COMMIT(); CP_WAIT1(); }
        else                 { CP_WAIT0(); }
        __syncthreads();
        chunk_r(acc, sbase + (ci & 1) * STB_R, mw, nw, lane);
        __syncthreads();
    }

    const int mfrag = mw + (lane >> 2);
    const int nfrag = nw + (lane & 3) * 2;
#pragma unroll
    for (int mi = 0; mi < 4; mi++) {
        const int r0 = m0 + mfrag + mi * 16;
#pragma unroll
        for (int nj = 0; nj < 4; nj++) {
            const int nl = nfrag + nj * 8;
            const float* c = acc[mi][nj];
            float b0 = bias[nl], b1v = bias[nl + 1];
            float2 o0, o1;
            o0.x = gelu_f(c[0] + b0);
            o0.y = gelu_f(c[1] + b1v);
            o1.x = gelu_f(c[2] + b0);
            o1.y = gelu_f(c[3] + b1v);
            *(float2*)&ob[(size_t)r0 * out_ld + ocol + nl]       = o0;
            *(float2*)&ob[(size_t)(r0 + 8) * out_ld + ocol + nl] = o1;
        }
    }
}

// ---------------------------------------------------------------------------
extern "C" void kernel_launch(void* const* d_in, const int* in_sizes, int n_in,
                              void* d_out, int out_size)
{
    const float* hidden  = (const float*)d_in[0];
    const float* feat    = (const float*)d_in[1];
    const float* ln_g    = (const float*)d_in[2];
    const float* ln_b    = (const float*)d_in[3];
    const float* stage_W = (const float*)d_in[4];
    const float* stage_b = (const float*)d_in[5];
    const float* bproj_W = (const float*)d_in[6];
    const float* bproj_b = (const float*)d_in[7];
    const float* br_W1   = (const float*)d_in[8];
    const float* br_b1   = (const float*)d_in[9];
    const float* br_W2   = (const float*)d_in[10];
    const float* br_b2   = (const float*)d_in[11];
    const float* ir_W1   = (const float*)d_in[12];
    const float* ir_b1   = (const float*)d_in[13];
    const float* ir_W2   = (const float*)d_in[14];
    const float* ir_b2   = (const float*)d_in[15];
    const float* ex_W1   = (const float*)d_in[16];
    const float* ex_b1   = (const float*)d_in[17];
    const float* ex_W2   = (const float*)d_in[18];
    const float* ex_b2   = (const float*)d_in[19];
    const float* alpha   = (const float*)d_in[20];
    float* out = (float*)d_out;

    cudaFuncSetAttribute((const void*)ex1_kernel,
                         cudaFuncAttributeMaxDynamicSharedMemorySize, DSM_EX);
    cudaFuncSetAttribute((const void*)ex2_kernel,
                         cudaFuncAttributeMaxDynamicSharedMemorySize, DSM_EX);
    cudaFuncSetAttribute((const void*)router_mma,
                         cudaFuncAttributeMaxDynamicSharedMemorySize, DSM_RTR);

    prep_kernel<<<M_TOK, 256>>>(hidden, feat, ln_g, ln_b,
                                stage_W, stage_b, bproj_W, bproj_b);
    {
        dim3 g(DEH / 32, D_HID / 32, NE);
        transpose_split<1><<<g, 256>>>(ex_W1);
    }
    {
        dim3 g(D_HID / 32, NEH / 32, 1);
        transpose_split<2><<<g, 256>>>(ex_W2);
    }
    {
        dim3 g(DRH / 32, RIN / 32, 1);
        transpose_split<3><<<g, 256>>>(br_W1);
    }
    {
        dim3 g(DRH / 32, RIN / 32, NB);
        transpose_split<4><<<g, 256>>>(ir_W1);
    }
    {
        dim3 g(DRH / 128, M_TOK / 128, 1 + NB);
        router_mma<<<g, 256, DSM_RTR>>>(br_b1, ir_b1);
    }
    gate_kernel<<<M_TOK, 128>>>(br_W2, br_b2, ir_W2, ir_b2, out);
    sched_kernel<<<1, 32>>>();
    {
        dim3 g(DEH / 128, MAXTILES, 1);
        ex1_kernel<<<g, 256, DSM_EX>>>(ex_b1);
    }
    {
        dim3 g(D_HID / 128, MAXTILES, 1);
        ex2_kernel<<<g, 256, DSM_EX>>>();
    }
    combine_kernel<<<M_TOK, 256>>>(hidden, ex_b2, alpha, out);
}

// round 17
// speedup vs baseline: 3.8145x; 1.0421x over previous
#include <cuda_runtime.h>
#include <cuda_bf16.h>
#include <cuda_fp16.h>
#include <cstdint>

#define M_TOK 8192
#define D_HID 1024
#define F_FEAT 64
#define DFE 128
#define RIN 1152
#define DRH 256
#define NB 4
#define FPB 16
#define ES 4
#define NE 16
#define DEH 512
#define NEH (NE * DEH)

#define OFF_NH 0
#define OFF_GW (M_TOK * D_HID)
#define OFF_GL (OFF_GW + M_TOK * NE)
#define OFF_BW (OFF_GL + M_TOK * NE)
#define OFF_BL (OFF_BW + M_TOK * NB)
#define OFF_SD (OFF_BL + M_TOK * NB)

#define ECAP (M_TOK * 8)
#define MAXTILES 1040

typedef unsigned long long ull;
typedef __nv_bfloat16 bf16;
typedef __half fp16;

// ------------------------- scratch ------------------------------------------
__device__ float g_bh[M_TOK * DRH];
__device__ float g_ih[M_TOK * NB * DRH];
__device__ float g_gate[M_TOK * NE];
// router path (bf16 3-term — routers are error-critical, keep precise)
__device__ bf16 g_ah[M_TOK * D_HID];
__device__ bf16 g_al[M_TOK * D_HID];
__device__ bf16 g_sfe_h[M_TOK * DFE];
__device__ bf16 g_sfe_l[M_TOK * DFE];
__device__ bf16 g_bemb_h[M_TOK * NB * DFE];
__device__ bf16 g_bemb_l[M_TOK * NB * DFE];
__device__ bf16 g_wbr_h[DRH * RIN];
__device__ bf16 g_wbr_l[DRH * RIN];
__device__ bf16 g_wir_h[NB * DRH * RIN];
__device__ bf16 g_wir_l[NB * DRH * RIN];
// expert path (ex1: fp16 2-term; ex2: fp16 1-term)
__device__ fp16 g_xh[M_TOK * D_HID];
__device__ fp16 g_w1s_h[NEH * D_HID];
__device__ fp16 g_w1s_l[NEH * D_HID];
__device__ fp16 g_w2s_h[D_HID * NEH];
// sparse dispatch
__device__ int g_cnt[NE];
__device__ int g_off[NE + 1];
__device__ int g_list[NE * M_TOK];
__device__ int g_te[M_TOK * 8];
__device__ int g_tp[M_TOK * 8];
__device__ int g_tcnt[M_TOK];
__device__ int g_tile_e[MAXTILES];
__device__ int g_tile_m[MAXTILES];
__device__ int g_ntiles;
__device__ fp16 g_ehc[(size_t)(ECAP + 128) * DEH];
__device__ fp16 g_eo[(size_t)(ECAP + 128) * D_HID];

// ------------------------- helpers ------------------------------------------
__device__ __forceinline__ float gelu_f(float x) {
    return 0.5f * x * (1.0f + erff(x * 0.70710678118654752440f));
}
__device__ __forceinline__ void split_bf16(float v, bf16& h, bf16& l) {
    h = __float2bfloat16(v);
    l = __float2bfloat16(v - __bfloat162float(h));
}
__device__ __forceinline__ void split_fp16(float v, fp16& h, fp16& l) {
    h = __float2half(v);
    l = __float2half(v - __half2float(h));
}
__device__ __forceinline__ uint32_t smem_u32(const void* p) {
    uint32_t a;
    asm("{ .reg .u64 t; cvta.to.shared.u64 t, %1; cvt.u32.u64 %0, t; }"
        : "=r"(a) : "l"(p));
    return a;
}
__device__ __forceinline__ void cpa16(uint32_t s, const void* g) {
    asm volatile("cp.async.cg.shared.global [%0], [%1], 16;" :: "r"(s), "l"(g));
}
#define CP_COMMIT() asm volatile("cp.async.commit_group;" ::: "memory")
#define CP_WAIT1()  asm volatile("cp.async.wait_group 1;" ::: "memory")
#define CP_WAIT0()  asm volatile("cp.async.wait_group 0;" ::: "memory")

__device__ __forceinline__ void ldsm4(uint32_t* r, uint32_t addr) {
    asm volatile("ldmatrix.sync.aligned.m8n8.x4.shared.b16 {%0,%1,%2,%3}, [%4];"
        : "=r"(r[0]), "=r"(r[1]), "=r"(r[2]), "=r"(r[3]) : "r"(addr));
}
__device__ __forceinline__ void mma_bf(float* c, const uint32_t* a, const uint32_t* b) {
    asm volatile("mma.sync.aligned.m16n8k16.row.col.f32.bf16.bf16.f32 "
        "{%0,%1,%2,%3}, {%4,%5,%6,%7}, {%8,%9}, {%0,%1,%2,%3};"
        : "+f"(c[0]), "+f"(c[1]), "+f"(c[2]), "+f"(c[3])
        : "r"(a[0]), "r"(a[1]), "r"(a[2]), "r"(a[3]), "r"(b[0]), "r"(b[1]));
}
__device__ __forceinline__ void mma_fp(float* c, const uint32_t* a, const uint32_t* b) {
    asm volatile("mma.sync.aligned.m16n8k16.row.col.f32.f16.f16.f32 "
        "{%0,%1,%2,%3}, {%4,%5,%6,%7}, {%8,%9}, {%0,%1,%2,%3};"
        : "+f"(c[0]), "+f"(c[1]), "+f"(c[2]), "+f"(c[3])
        : "r"(a[0]), "r"(a[1]), "r"(a[2]), "r"(a[3]), "r"(b[0]), "r"(b[1]));
}

// ---------------------------------------------------------------------------
// Kernel 1: LN + embeddings + counter zeroing
// ---------------------------------------------------------------------------
__global__ void __launch_bounds__(256) prep_kernel(
    const float* __restrict__ hidden, const float* __restrict__ feat,
    const float* __restrict__ ln_g, const float* __restrict__ ln_b,
    const float* __restrict__ stage_W, const float* __restrict__ stage_b,
    const float* __restrict__ bproj_W, const float* __restrict__ bproj_b)
{
    const int t = blockIdx.x, tid = threadIdx.x;
    if (t == 0 && tid < NE) g_cnt[tid] = 0;
    __shared__ float red[256];
    __shared__ float sfeat[F_FEAT];
    const float* hrow = hidden + (size_t)t * D_HID;
    float x[4], s = 0.f;
#pragma unroll
    for (int i = 0; i < 4; i++) { x[i] = hrow[tid + 256 * i]; s += x[i]; }
    if (tid < F_FEAT) sfeat[tid] = feat[(size_t)t * F_FEAT + tid];
    red[tid] = s;
    __syncthreads();
    for (int off = 128; off > 0; off >>= 1) {
        if (tid < off) red[tid] += red[tid + off];
        __syncthreads();
    }
    const float mu = red[0] * (1.0f / 1024.0f);
    __syncthreads();
    float v = 0.f;
#pragma unroll
    for (int i = 0; i < 4; i++) { float d = x[i] - mu; v += d * d; }
    red[tid] = v;
    __syncthreads();
    for (int off = 128; off > 0; off >>= 1) {
        if (tid < off) red[tid] += red[tid + off];
        __syncthreads();
    }
    const float rstd = rsqrtf(red[0] * (1.0f / 1024.0f) + 1e-5f);
#pragma unroll
    for (int i = 0; i < 4; i++) {
        int d = tid + 256 * i;
        float hv = (x[i] - mu) * rstd * ln_g[d] + ln_b[d];
        bf16 hi, lo; split_bf16(hv, hi, lo);
        g_ah[(size_t)t * D_HID + d] = hi;
        g_al[(size_t)t * D_HID + d] = lo;
        g_xh[(size_t)t * D_HID + d] = __float2half(hv);
    }
    if (tid < DFE) {
        float acc = stage_b[tid];
#pragma unroll
        for (int f = 0; f < F_FEAT; f++) acc += sfeat[f] * stage_W[f * DFE + tid];
        bf16 hi, lo; split_bf16(acc, hi, lo);
        g_sfe_h[(size_t)t * DFE + tid] = hi;
        g_sfe_l[(size_t)t * DFE + tid] = lo;
    }
    for (int idx = tid; idx < NB * DFE; idx += 256) {
        int g = idx >> 7, j = idx & 127;
        float acc = bproj_b[g * DFE + j];
#pragma unroll
        for (int f = 0; f < FPB; f++)
            acc += sfeat[g * FPB + f] * bproj_W[(g * FPB + f) * DFE + j];
        bf16 hi, lo; split_bf16(acc, hi, lo);
        g_bemb_h[(size_t)t * (NB * DFE) + idx] = hi;
        g_bemb_l[(size_t)t * (NB * DFE) + idx] = lo;
    }
}

// ---------------------------------------------------------------------------
// Transpose + split.  W=1: ex_W1 -> w1s fp16 hi/lo;  W=2: ex_W2 -> w2s fp16 (hi only);
// W=3: br_W1 -> wbr bf16 hi/lo;  W=4: ir_W1 -> wir bf16 hi/lo.
// ---------------------------------------------------------------------------
template <int W>
__global__ void __launch_bounds__(256) transpose_split(const float* __restrict__ src)
{
    __shared__ float tl[32][33];
    const int z = blockIdx.z;
    const int C = (W == 1) ? DEH : ((W == 2) ? D_HID : DRH);
    const size_t dld = (W == 1) ? D_HID : ((W == 2) ? NEH : RIN);
    const size_t srcz = (W == 1) ? (size_t)D_HID * DEH : ((W == 4) ? (size_t)RIN * DRH : 0);
    const int dstz = (W == 1) ? DEH : ((W == 4) ? DRH : 0);
    const float* s = src + (size_t)z * srcz;
    const int r0 = blockIdx.y * 32, c0 = blockIdx.x * 32;
    const int tx = threadIdx.x & 31, ty = threadIdx.x >> 5;
#pragma unroll
    for (int i = 0; i < 4; i++)
        tl[ty + i * 8][tx] = s[(size_t)(r0 + ty + i * 8) * C + c0 + tx];
    __syncthreads();
#pragma unroll
    for (int i = 0; i < 4; i++) {
        int c = c0 + ty + i * 8;
        float v = tl[tx][ty + i * 8];
        size_t o = ((size_t)z * dstz + c) * dld + r0 + tx;
        if (W == 1) {
            fp16 hi, lo; split_fp16(v, hi, lo);
            g_w1s_h[o] = hi; g_w1s_l[o] = lo;
        } else if (W == 2) {
            g_w2s_h[o] = __float2half(v);
        } else if (W == 3) {
            bf16 hi, lo; split_bf16(v, hi, lo);
            g_wbr_h[o] = hi; g_wbr_l[o] = lo;
        } else {
            bf16 hi, lo; split_bf16(v, hi, lo);
            g_wir_h[o] = hi; g_wir_l[o] = lo;
        }
    }
}

// ---------------------------------------------------------------------------
// Gate kernel: 4 tokens/block, router W2 staged in SMEM.
// ---------------------------------------------------------------------------
__device__ __forceinline__ void top2sm4(const float* s, float* w) {
    float m1 = fmaxf(fmaxf(s[0], s[1]), fmaxf(s[2], s[3]));
    float m2 = -3.0e38f;
    bool used = false;
#pragma unroll
    for (int i = 0; i < 4; i++) {
        if (!used && s[i] == m1) used = true;
        else m2 = fmaxf(m2, s[i]);
    }
    float e[4], den = 0.f;
#pragma unroll
    for (int i = 0; i < 4; i++) {
        e[i] = (s[i] >= m2) ? expf(s[i] - m1) : 0.f;
        den += e[i];
    }
    float inv = 1.0f / den;
#pragma unroll
    for (int i = 0; i < 4; i++) w[i] = e[i] * inv;
}

__global__ void __launch_bounds__(256) gate_kernel(
    const float* __restrict__ br_W2, const float* __restrict__ br_b2,
    const float* __restrict__ ir_W2, const float* __restrict__ ir_b2,
    float* __restrict__ out)
{
    const int t0 = blockIdx.x * 4, tid = threadIdx.x;
    __shared__ float swbr[DRH * NB];          // 1024
    __shared__ float swir[NB * DRH * ES];     // 4096
    __shared__ float sbh[4][DRH];
    __shared__ float sih[4][NB * DRH];
    __shared__ float slog[4][20];
    for (int i = tid; i < DRH * NB; i += 256) swbr[i] = br_W2[i];
    for (int i = tid; i < NB * DRH * ES; i += 256) swir[i] = ir_W2[i];
    for (int i = tid; i < 4 * DRH; i += 256)
        sbh[i >> 8][i & 255] = g_bh[(size_t)(t0 + (i >> 8)) * DRH + (i & 255)];
    for (int i = tid; i < 4 * NB * DRH; i += 256)
        sih[i >> 10][i & 1023] = g_ih[(size_t)(t0 + (i >> 10)) * NB * DRH + (i & 1023)];
    __syncthreads();

    const int wid = tid >> 5, lane = tid & 31;
    const int ti = wid >> 1, half = wid & 1;
    for (int d = half; d < 20; d += 2) {
        float s = 0.f;
        if (d < 4) {
            for (int k = lane; k < DRH; k += 32) s += sbh[ti][k] * swbr[k * NB + d];
        } else {
            int g = (d - 4) >> 2, e = (d - 4) & 3;
            for (int k = lane; k < DRH; k += 32)
                s += sih[ti][g * DRH + k] * swir[g * DRH * ES + k * ES + e];
        }
#pragma unroll
        for (int off = 16; off; off >>= 1) s += __shfl_xor_sync(0xffffffffu, s, off);
        if (lane == 0) slog[ti][d] = s + ((d < 4) ? br_b2[d] : ir_b2[d - 4]);
    }
    __syncthreads();
    if (tid < 4) {
        const int t = t0 + tid;
        float bl[4], bw[4], il[16], iw[16], gwv[16];
#pragma unroll
        for (int i = 0; i < 4; i++) bl[i] = slog[tid][i];
#pragma unroll
        for (int i = 0; i < 16; i++) il[i] = slog[tid][4 + i];
        top2sm4(bl, bw);
#pragma unroll
        for (int g = 0; g < 4; g++) top2sm4(&il[g * 4], &iw[g * 4]);
#pragma unroll
        for (int g = 0; g < 4; g++) {
            out[OFF_BW + (size_t)t * NB + g] = bw[g];
            out[OFF_BL + (size_t)t * NB + g] = bl[g];
#pragma unroll
            for (int e = 0; e < 4; e++) {
                int idx = g * 4 + e;
                float gw = bw[g] * iw[idx];
                gwv[idx] = gw;
                out[OFF_GW + (size_t)t * NE + idx] = gw;
                out[OFF_GL + (size_t)t * NE + idx] = bl[g] + il[idx];
                g_gate[(size_t)t * NE + idx] = gw;
            }
        }
        int cnt = 0;
#pragma unroll
        for (int e = 0; e < NE; e++) {
            if (gwv[e] > 0.f) {
                int p = atomicAdd(&g_cnt[e], 1);
                g_list[e * M_TOK + p] = t;
                if (cnt < 8) { g_te[t * 8 + cnt] = e; g_tp[t * 8 + cnt] = p; }
                cnt++;
            }
        }
        g_tcnt[t] = cnt < 8 ? cnt : 8;
    }
}

// single-block scheduler
__global__ void sched_kernel() {
    if (threadIdx.x == 0) {
        int off = 0;
        for (int e = 0; e < NE; e++) { g_off[e] = off; off += g_cnt[e]; }
        g_off[NE] = off;
        int nt = 0;
        for (int e = 0; e < NE; e++) {
            int T = (g_cnt[e] + 127) >> 7;
            for (int m = 0; m < T && nt < MAXTILES; m++) {
                g_tile_e[nt] = e; g_tile_m[nt] = m; nt++;
            }
        }
        g_ntiles = nt;
    }
}

// ---------------------------------------------------------------------------
// Tile constants.  CTA 128x128, K-chunk 32, 8 warps (warp 64x32).
// ---------------------------------------------------------------------------
#define LDT 40
#define TILE_B 10240
#define STB1 (3 * TILE_B)             // ex1 / router-f16 stage: A+Bh+Bl
#define STB2 (2 * TILE_B)             // ex2 stage: A+Bh
#define STB_R (4 * TILE_B)            // router stage: Ah+Al+Bh+Bl
#define DSM_EX1 (3 * STB1)            // 92160
#define DSM_EX2 (3 * STB2)            // 61440
#define DSM_RTR (3 * STB_R)           // 122880

// 2-term fp16 chunk (A, Bh, Bl resident)
__device__ __forceinline__ void chunk_e2(
    float (*acc)[4][4], uint32_t ab, int mw, int nw, int lane)
{
    const uint32_t bb = ab + TILE_B;
#pragma unroll
    for (int ks = 0; ks < 32; ks += 16) {
        uint32_t ah[4][4], bhf[2][4], blf[2][4];
#pragma unroll
        for (int mi = 0; mi < 4; mi++) {
            uint32_t ra = ab + (uint32_t)((mw + mi * 16 + (lane & 15)) * LDT
                                          + ks + ((lane >> 4) & 1) * 8) * 2;
            ldsm4(ah[mi], ra);
        }
#pragma unroll
        for (int pj = 0; pj < 2; pj++) {
            uint32_t rb = bb + (uint32_t)((nw + pj * 16 + ((lane >> 4) & 1) * 8
                                           + (lane & 7)) * LDT
                                          + ks + ((lane >> 3) & 1) * 8) * 2;
            ldsm4(bhf[pj], rb);
            ldsm4(blf[pj], rb + TILE_B);
        }
#pragma unroll
        for (int mi = 0; mi < 4; mi++)
#pragma unroll
            for (int nj = 0; nj < 4; nj++) {
                const int pj = nj >> 1, sb = (nj & 1) * 2;
                mma_fp(acc[mi][nj], ah[mi], &bhf[pj][sb]);
                mma_fp(acc[mi][nj], ah[mi], &blf[pj][sb]);
            }
    }
}

// 1-term fp16 chunk (A, Bh resident)
__device__ __forceinline__ void chunk_e1(
    float (*acc)[4][4], uint32_t ab, int mw, int nw, int lane)
{
    const uint32_t bb = ab + TILE_B;
#pragma unroll
    for (int ks = 0; ks < 32; ks += 16) {
        uint32_t ah[4][4], bhf[2][4];
#pragma unroll
        for (int mi = 0; mi < 4; mi++) {
            uint32_t ra = ab + (uint32_t)((mw + mi * 16 + (lane & 15)) * LDT
                                          + ks + ((lane >> 4) & 1) * 8) * 2;
            ldsm4(ah[mi], ra);
        }
#pragma unroll
        for (int pj = 0; pj < 2; pj++) {
            uint32_t rb = bb + (uint32_t)((nw + pj * 16 + ((lane >> 4) & 1) * 8
                                           + (lane & 7)) * LDT
                                          + ks + ((lane >> 3) & 1) * 8) * 2;
            ldsm4(bhf[pj], rb);
        }
#pragma unroll
        for (int mi = 0; mi < 4; mi++)
#pragma unroll
            for (int nj = 0; nj < 4; nj++)
                mma_fp(acc[mi][nj], ah[mi], &bhf[nj >> 1][(nj & 1) * 2]);
    }
}

// 3-term bf16 chunk (Ah, Al, Bh, Bl resident)
__device__ __forceinline__ void chunk_r(
    float (*acc)[4][4], uint32_t ab, int mw, int nw, int lane)
{
    const uint32_t bb = ab + 2 * TILE_B;
#pragma unroll
    for (int ks = 0; ks < 32; ks += 16) {
        uint32_t ah[4][4], al[4][4], bhf[2][4], blf[2][4];
#pragma unroll
        for (int mi = 0; mi < 4; mi++) {
            uint32_t ra = ab + (uint32_t)((mw + mi * 16 + (lane & 15)) * LDT
                                          + ks + ((lane >> 4) & 1) * 8) * 2;
            ldsm4(ah[mi], ra);
            ldsm4(al[mi], ra + TILE_B);
        }
#pragma unroll
        for (int pj = 0; pj < 2; pj++) {
            uint32_t rb = bb + (uint32_t)((nw + pj * 16 + ((lane >> 4) & 1) * 8
                                           + (lane & 7)) * LDT
                                          + ks + ((lane >> 3) & 1) * 8) * 2;
            ldsm4(bhf[pj], rb);
            ldsm4(blf[pj], rb + TILE_B);
        }
#pragma unroll
        for (int mi = 0; mi < 4; mi++)
#pragma unroll
            for (int nj = 0; nj < 4; nj++) {
                const int pj = nj >> 1, sb = (nj & 1) * 2;
                mma_bf(acc[mi][nj], ah[mi], &bhf[pj][sb]);
                mma_bf(acc[mi][nj], ah[mi], &blf[pj][sb]);
                mma_bf(acc[mi][nj], al[mi], &bhf[pj][sb]);
            }
    }
}

// ---------------------------------------------------------------------------
// ex1 grouped GEMM (2-term): gathered tokens x W1[e] -> ehc; 1-sync 3-stage.
// ---------------------------------------------------------------------------
__global__ void __launch_bounds__(256) ex1_kernel(const float* __restrict__ ex_b1)
{
    extern __shared__ fp16 dsm[];
    __shared__ int stok[128];
    const uint32_t sbase = smem_u32(dsm);
    const int tid = threadIdx.x;
    const int wid = tid >> 5, lane = tid & 31;
    if (blockIdx.y >= g_ntiles) return;
    const int e = g_tile_e[blockIdx.y], mt = g_tile_m[blockIdx.y];
    const int cnt = g_cnt[e], off = g_off[e];
    const int base = mt * 128;
    if (tid < 128) {
        int idx = base + tid;
        stok[tid] = g_list[e * M_TOK + (idx < cnt ? idx : cnt - 1)];
    }
    __syncthreads();
    const int n0 = blockIdx.x * 128;
    const fp16* Bh = g_w1s_h + (size_t)(e * DEH + n0) * D_HID;
    const fp16* Bl = g_w1s_l + (size_t)(e * DEH + n0) * D_HID;

    const int mw = (wid >> 2) * 64;
    const int nw = (wid & 3) * 32;

    float acc[4][4][4];
#pragma unroll
    for (int a = 0; a < 4; a++)
#pragma unroll
        for (int b = 0; b < 4; b++)
#pragma unroll
            for (int c = 0; c < 4; c++) acc[a][b][c] = 0.f;

    auto load1 = [&](int ci) {
        const uint32_t sb = sbase + (ci % 3) * STB1;
        const int k0 = ci * 32;
#pragma unroll
        for (int i = 0; i < 2; i++) {
            int q = i * 256 + tid;
            int row = q >> 2, seg = q & 3;
            uint32_t so = (uint32_t)(row * LDT + seg * 8) * 2;
            cpa16(sb + so, g_xh + (size_t)stok[row] * D_HID + k0 + seg * 8);
            cpa16(sb + TILE_B + so,     Bh + (size_t)row * D_HID + k0 + seg * 8);
            cpa16(sb + 2 * TILE_B + so, Bl + (size_t)row * D_HID + k0 + seg * 8);
        }
    };

    const int nchunk = D_HID / 32;   // 32
    load1(0); CP_COMMIT();
    load1(1); CP_COMMIT();
    for (int ci = 0; ci < nchunk; ci++) {
        if (ci + 1 < nchunk) CP_WAIT1(); else CP_WAIT0();
        __syncthreads();
        chunk_e2(acc, sbase + (ci % 3) * STB1, mw, nw, lane);
        if (ci + 2 < nchunk) { load1(ci + 2); CP_COMMIT(); }
    }

    const int mfrag = mw + (lane >> 2);
    const int nfrag = nw + (lane & 3) * 2;
#pragma unroll
    for (int mi = 0; mi < 4; mi++) {
        const int r0 = mfrag + mi * 16;
#pragma unroll
        for (int h = 0; h < 2; h++) {
            const int r = r0 + h * 8;
            if (base + r >= cnt) continue;
            const int t = stok[r];
            const float gv = g_gate[(size_t)t * NE + e];
#pragma unroll
            for (int nj = 0; nj < 4; nj++) {
                const int nl = nfrag + nj * 8;
                const float* c = acc[mi][nj];
                float o0 = gelu_f(c[h * 2]     + ex_b1[e * DEH + n0 + nl])     * gv;
                float o1 = gelu_f(c[h * 2 + 1] + ex_b1[e * DEH + n0 + nl + 1]) * gv;
                *(__half2*)&g_ehc[(size_t)(off + base + r) * DEH + n0 + nl] =
                    __floats2half2_rn(o0, o1);
            }
        }
    }
}

// ---------------------------------------------------------------------------
// ex2 grouped GEMM (1-term): compact ehc x W2[e] -> compact eo (fp16)
// ---------------------------------------------------------------------------
__global__ void __launch_bounds__(256) ex2_kernel()
{
    extern __shared__ fp16 dsm[];
    const uint32_t sbase = smem_u32(dsm);
    const int tid = threadIdx.x;
    const int wid = tid >> 5, lane = tid & 31;
    if (blockIdx.y >= g_ntiles) return;
    const int e = g_tile_e[blockIdx.y], mt = g_tile_m[blockIdx.y];
    const int cnt = g_cnt[e], off = g_off[e];
    const int base = mt * 128;
    const int n0 = blockIdx.x * 128;

    const fp16* A  = g_ehc + (size_t)(off + base) * DEH;
    const fp16* Bh = g_w2s_h + (size_t)n0 * NEH + e * DEH;

    const int mw = (wid >> 2) * 64;
    const int nw = (wid & 3) * 32;

    float acc[4][4][4];
#pragma unroll
    for (int a = 0; a < 4; a++)
#pragma unroll
        for (int b = 0; b < 4; b++)
#pragma unroll
            for (int c = 0; c < 4; c++) acc[a][b][c] = 0.f;

    auto load2 = [&](int ci) {
        const uint32_t sb = sbase + (ci % 3) * STB2;
        const int k0 = ci * 32;
#pragma unroll
        for (int i = 0; i < 2; i++) {
            int q = i * 256 + tid;
            int row = q >> 2, seg = q & 3;
            uint32_t so = (uint32_t)(row * LDT + seg * 8) * 2;
            cpa16(sb + so,          A  + (size_t)row * DEH + k0 + seg * 8);
            cpa16(sb + TILE_B + so, Bh + (size_t)row * NEH + k0 + seg * 8);
        }
    };

    const int nchunk = DEH / 32;   // 16
    load2(0); CP_COMMIT();
    load2(1); CP_COMMIT();
    for (int ci = 0; ci < nchunk; ci++) {
        if (ci + 1 < nchunk) CP_WAIT1(); else CP_WAIT0();
        __syncthreads();
        chunk_e1(acc, sbase + (ci % 3) * STB2, mw, nw, lane);
        if (ci + 2 < nchunk) { load2(ci + 2); CP_COMMIT(); }
    }

    const int mfrag = mw + (lane >> 2);
    const int nfrag = nw + (lane & 3) * 2;
#pragma unroll
    for (int mi = 0; mi < 4; mi++) {
        const int r0 = mfrag + mi * 16;
#pragma unroll
        for (int h = 0; h < 2; h++) {
            const int r = r0 + h * 8;
            if (base + r >= cnt) continue;
            const size_t go = (size_t)(off + base + r) * D_HID + n0;
#pragma unroll
            for (int nj = 0; nj < 4; nj++) {
                const int nl = nfrag + nj * 8;
                const float* c = acc[mi][nj];
                *(__half2*)&g_eo[go + nl] = __floats2half2_rn(c[h * 2], c[h * 2 + 1]);
            }
        }
    }
}

// ---------------------------------------------------------------------------
// combine
// ---------------------------------------------------------------------------
__global__ void __launch_bounds__(256) combine_kernel(
    const float* __restrict__ hidden, const float* __restrict__ ex_b2,
    const float* __restrict__ alpha_p, float* __restrict__ out)
{
    const int t = blockIdx.x, tid = threadIdx.x;
    __shared__ int se[8], sp[8];
    __shared__ int scnt_s;
    if (tid < 8) { se[tid] = g_te[t * 8 + tid]; sp[tid] = g_tp[t * 8 + tid]; }
    if (tid == 0) scnt_s = g_tcnt[t];
    __syncthreads();
    const int scnt = scnt_s;
    const int d = tid * 4;
    float4 acc = {0.f, 0.f, 0.f, 0.f};
    for (int s = 0; s < scnt; s++) {
        const int e = se[s];
        const size_t entry = (size_t)g_off[e] + sp[s];
        const __half2* p = (const __half2*)&g_eo[entry * D_HID + d];
        float2 v0 = __half22float2(p[0]);
        float2 v1 = __half22float2(p[1]);
        const float gw = g_gate[(size_t)t * NE + e];
        float4 b = *(const float4*)&ex_b2[e * D_HID + d];
        acc.x += v0.x + gw * b.x; acc.y += v0.y + gw * b.y;
        acc.z += v1.x + gw * b.z; acc.w += v1.y + gw * b.w;
    }
    const float alpha = *alpha_p;
    float4 h = *(const float4*)&hidden[(size_t)t * D_HID + d];
    float4 nh;
    nh.x = h.x + alpha * acc.x; nh.y = h.y + alpha * acc.y;
    nh.z = h.z + alpha * acc.z; nh.w = h.w + alpha * acc.w;
    *(float4*)&out[OFF_SD + (size_t)t * D_HID + d] = acc;
    *(float4*)&out[OFF_NH + (size_t)t * D_HID + d] = nh;
}

// ---------------------------------------------------------------------------
// Router GEMM1 (bf16 3-term), 1-sync 3-stage.
// ---------------------------------------------------------------------------
__global__ void __launch_bounds__(256) router_mma(
    const float* __restrict__ br_b1, const float* __restrict__ ir_b1)
{
    extern __shared__ fp16 dsm[];
    const uint32_t sbase = smem_u32(dsm);
    const int tid = threadIdx.x;
    const int wid = tid >> 5, lane = tid & 31;
    const int m0 = blockIdx.y * 128;
    const int nt0 = blockIdx.x * 128;
    const int z = blockIdx.z;

    const bf16 *EAh, *EAl, *Bh, *Bl;
    const float* bias;
    float* ob;
    int lda2, out_ld, ocol;
    if (z == 0) {
        EAh = g_sfe_h; EAl = g_sfe_l; lda2 = DFE;
        Bh = g_wbr_h + (size_t)nt0 * RIN; Bl = g_wbr_l + (size_t)nt0 * RIN;
        bias = br_b1 + nt0;
        ob = g_bh; out_ld = DRH; ocol = nt0;
    } else {
        const int g = z - 1;
        EAh = g_bemb_h + g * DFE; EAl = g_bemb_l + g * DFE; lda2 = NB * DFE;
        Bh = g_wir_h + ((size_t)g * DRH + nt0) * RIN;
        Bl = g_wir_l + ((size_t)g * DRH + nt0) * RIN;
        bias = ir_b1 + g * DRH + nt0;
        ob = g_ih; out_ld = NB * DRH; ocol = g * DRH + nt0;
    }

    const int mw = (wid >> 2) * 64;
    const int nw = (wid & 3) * 32;
    const int nchunk = RIN / 32;   // 36

    float acc[4][4][4];
#pragma unroll
    for (int a = 0; a < 4; a++)
#pragma unroll
        for (int b = 0; b < 4; b++)
#pragma unroll
            for (int c = 0; c < 4; c++) acc[a][b][c] = 0.f;

    auto load_rt = [&](int ci) {
        const uint32_t sb = sbase + (ci % 3) * STB_R;
        const int k0 = ci * 32;
        const bf16 *Ah, *Al;
        int lda;
        if (k0 < D_HID) {
            Ah = g_ah + (size_t)m0 * D_HID + k0;
            Al = g_al + (size_t)m0 * D_HID + k0;
            lda = D_HID;
        } else {
            Ah = EAh + (size_t)m0 * lda2 + (k0 - D_HID);
            Al = EAl + (size_t)m0 * lda2 + (k0 - D_HID);
            lda = lda2;
        }
#pragma unroll
        for (int i = 0; i < 2; i++) {
            int q = i * 256 + tid;
            int row = q >> 2, seg = q & 3;
            uint32_t so = (uint32_t)(row * LDT + seg * 8) * 2;
            cpa16(sb + so,              Ah + (size_t)row * lda + seg * 8);
            cpa16(sb + TILE_B + so,     Al + (size_t)row * lda + seg * 8);
            cpa16(sb + 2 * TILE_B + so, Bh + (size_t)row * RIN + k0 + seg * 8);
            cpa16(sb + 3 * TILE_B + so, Bl + (size_t)row * RIN + k0 + seg * 8);
        }
    };

    load_rt(0); CP_COMMIT();
    load_rt(1); CP_COMMIT();
    for (int ci = 0; ci < nchunk; ci++) {
        if (ci + 1 < nchunk) CP_WAIT1(); else CP_WAIT0();
        __syncthreads();
        chunk_r(acc, sbase + (ci % 3) * STB_R, mw, nw, lane);
        if (ci + 2 < nchunk) { load_rt(ci + 2); CP_COMMIT(); }
    }

    const int mfrag = mw + (lane >> 2);
    const int nfrag = nw + (lane & 3) * 2;
#pragma unroll
    for (int mi = 0; mi < 4; mi++) {
        const int r0 = m0 + mfrag + mi * 16;
#pragma unroll
        for (int nj = 0; nj < 4; nj++) {
            const int nl = nfrag + nj * 8;
            const float* c = acc[mi][nj];
            float b0 = bias[nl], b1v = bias[nl + 1];
            float2 o0, o1;
            o0.x = gelu_f(c[0] + b0);
            o0.y = gelu_f(c[1] + b1v);
            o1.x = gelu_f(c[2] + b0);
            o1.y = gelu_f(c[3] + b1v);
            *(float2*)&ob[(size_t)r0 * out_ld + ocol + nl]       = o0;
            *(float2*)&ob[(size_t)(r0 + 8) * out_ld + ocol + nl] = o1;
        }
    }
}

// ---------------------------------------------------------------------------
extern "C" void kernel_launch(void* const* d_in, const int* in_sizes, int n_in,
                              void* d_out, int out_size)
{
    const float* hidden  = (const float*)d_in[0];
    const float* feat    = (const float*)d_in[1];
    const float* ln_g    = (const float*)d_in[2];
    const float* ln_b    = (const float*)d_in[3];
    const float* stage_W = (const float*)d_in[4];
    const float* stage_b = (const float*)d_in[5];
    const float* bproj_W = (const float*)d_in[6];
    const float* bproj_b = (const float*)d_in[7];
    const float* br_W1   = (const float*)d_in[8];
    const float* br_b1   = (const float*)d_in[9];
    const float* br_W2   = (const float*)d_in[10];
    const float* br_b2   = (const float*)d_in[11];
    const float* ir_W1   = (const float*)d_in[12];
    const float* ir_b1   = (const float*)d_in[13];
    const float* ir_W2   = (const float*)d_in[14];
    const float* ir_b2   = (const float*)d_in[15];
    const float* ex_W1   = (const float*)d_in[16];
    const float* ex_b1   = (const float*)d_in[17];
    const float* ex_W2   = (const float*)d_in[18];
    const float* ex_b2   = (const float*)d_in[19];
    const float* alpha   = (const float*)d_in[20];
    float* out = (float*)d_out;

    cudaFuncSetAttribute((const void*)ex1_kernel,
                         cudaFuncAttributeMaxDynamicSharedMemorySize, DSM_EX1);
    cudaFuncSetAttribute((const void*)ex2_kernel,
                         cudaFuncAttributeMaxDynamicSharedMemorySize, DSM_EX2);
    cudaFuncSetAttribute((const void*)router_mma,
                         cudaFuncAttributeMaxDynamicSharedMemorySize, DSM_RTR);

    prep_kernel<<<M_TOK, 256>>>(hidden, feat, ln_g, ln_b,
                                stage_W, stage_b, bproj_W, bproj_b);
    {
        dim3 g(DEH / 32, D_HID / 32, NE);
        transpose_split<1><<<g, 256>>>(ex_W1);
    }
    {
        dim3 g(D_HID / 32, NEH / 32, 1);
        transpose_split<2><<<g, 256>>>(ex_W2);
    }
    {
        dim3 g(DRH / 32, RIN / 32, 1);
        transpose_split<3><<<g, 256>>>(br_W1);
    }
    {
        dim3 g(DRH / 32, RIN / 32, NB);
        transpose_split<4><<<g, 256>>>(ir_W1);
    }
    {
        dim3 g(DRH / 128, M_TOK / 128, 1 + NB);
        router_mma<<<g, 256, DSM_RTR>>>(br_b1, ir_b1);
    }
    gate_kernel<<<M_TOK / 4, 256>>>(br_W2, br_b2, ir_W2, ir_b2, out);
    sched_kernel<<<1, 32>>>();
    {
        dim3 g(DEH / 128, MAXTILES, 1);
        ex1_kernel<<<g, 256, DSM_EX1>>>(ex_b1);
    }
    {
        dim3 g(D_HID / 128, MAXTILES, 1);
        ex2_kernel<<<g, 256, DSM_EX2>>>();
    }
    combine_kernel<<<M_TOK, 256>>>(hidden, ex_b2, alpha, out);
}